// round 2
// baseline (speedup 1.0000x reference)
#include <cuda_runtime.h>
#include <cuda_bf16.h>
#include <math.h>

// ---------------------------------------------------------------------------
// Problem constants
// ---------------------------------------------------------------------------
#define BB 4
#define SS 2048
#define DD 1024
#define HH 16
#define DH 64
#define FF 4096
#define NN (BB * SS)          // 8192 rows
#define EPS 1e-6f
#define THRESH 0.15f
#define SCALE 0.125f          // 1/sqrt(64)

// ---------------------------------------------------------------------------
// Scratch (static __device__ arrays; no allocation allowed)
// ---------------------------------------------------------------------------
__device__ float g_x2  [NN * DD];   // norm1(x)
__device__ float g_q   [NN * DD];
__device__ float g_k   [NN * DD];
__device__ float g_v   [NN * DD];
__device__ float g_attn[NN * DD];
__device__ float g_xres[NN * DD];   // x + attn
__device__ float g_x2b [NN * DD];   // masked norm2(xres)
__device__ float g_h   [NN * FF];   // relu(ffn1)

// ---------------------------------------------------------------------------
// LayerNorm (+optional residual-in, +optional residual-out, +optional mask)
// one block (256 threads) per row, D = 1024 (4 floats / thread, float4)
// std is ddof=1, eps added to std (matches reference)
// ---------------------------------------------------------------------------
__global__ __launch_bounds__(256) void ln_kernel(
    const float* __restrict__ x,
    const float* __restrict__ resid,      // may be null
    float*       __restrict__ out_res,    // may be null
    float*       __restrict__ out_norm,
    const float* __restrict__ alpha,
    const float* __restrict__ beta,
    int apply_mask)
{
    __shared__ float red[256];
    const int n   = blockIdx.x;
    const int tid = threadIdx.x;
    const size_t off = (size_t)n * DD;
    const int d4 = tid * 4;

    float4 xv = *(const float4*)(x + off + d4);
    if (resid) {
        float4 rv = *(const float4*)(resid + off + d4);
        xv.x += rv.x; xv.y += rv.y; xv.z += rv.z; xv.w += rv.w;
    }
    if (out_res) *(float4*)(out_res + off + d4) = xv;

    float s = xv.x + xv.y + xv.z + xv.w;
    red[tid] = s;
    __syncthreads();
    #pragma unroll
    for (int st = 128; st > 0; st >>= 1) {
        if (tid < st) red[tid] += red[tid + st];
        __syncthreads();
    }
    const float mu = red[0] * (1.0f / DD);
    __syncthreads();

    float dx0 = xv.x - mu, dx1 = xv.y - mu, dx2 = xv.z - mu, dx3 = xv.w - mu;
    red[tid] = dx0*dx0 + dx1*dx1 + dx2*dx2 + dx3*dx3;
    __syncthreads();
    #pragma unroll
    for (int st = 128; st > 0; st >>= 1) {
        if (tid < st) red[tid] += red[tid + st];
        __syncthreads();
    }
    const float var = red[0] * (1.0f / (DD - 1));
    const float inv = 1.0f / (sqrtf(var) + EPS);

    float4 av = *(const float4*)(alpha + d4);
    float4 bv = *(const float4*)(beta  + d4);
    float4 y;
    y.x = av.x * dx0 * inv + bv.x;
    y.y = av.y * dx1 * inv + bv.y;
    y.z = av.z * dx2 * inv + bv.z;
    y.w = av.w * dx3 * inv + bv.w;
    if (apply_mask) {
        if (y.x < THRESH) y.x = 0.0f;
        if (y.y < THRESH) y.y = 0.0f;
        if (y.z < THRESH) y.z = 0.0f;
        if (y.w < THRESH) y.w = 0.0f;
    }
    *(float4*)(out_norm + off + d4) = y;
}

// ---------------------------------------------------------------------------
// SGEMM  C[N,O] = A[N,K] * W[O,K]^T + bias[O]   (both row-major, NT form)
// 128x128 block, BK=8, 256 threads, 8x8 per thread (split 4+4 fragments
// for conflict-free LDS.128).
// mode: 0 = plain, 1 = relu, 2 = add resid
// ---------------------------------------------------------------------------
__global__ __launch_bounds__(256, 2) void sgemm_nt(
    const float* __restrict__ A,
    const float* __restrict__ W,
    const float* __restrict__ bias,
    const float* __restrict__ resid,   // used when mode==2
    float*       __restrict__ C,
    int K, int ldc, int mode)
{
    __shared__ float As[8][128];
    __shared__ float Bs[8][128];

    const int tid  = threadIdx.x;
    const int ty   = tid >> 4;          // 0..15
    const int tx   = tid & 15;          // 0..15
    const int row0 = blockIdx.y * 128;
    const int col0 = blockIdx.x * 128;

    const int lrow = tid >> 1;          // 0..127
    const int lcol = (tid & 1) << 2;    // 0 or 4

    const float* Aptr = A + (size_t)(row0 + lrow) * K + lcol;
    const float* Wptr = W + (size_t)(col0 + lrow) * K + lcol;

    float acc[8][8];
    #pragma unroll
    for (int i = 0; i < 8; i++)
        #pragma unroll
        for (int j = 0; j < 8; j++) acc[i][j] = 0.0f;

    for (int k0 = 0; k0 < K; k0 += 8) {
        float4 av = *(const float4*)(Aptr + k0);
        float4 bv = *(const float4*)(Wptr + k0);
        As[lcol + 0][lrow] = av.x;
        As[lcol + 1][lrow] = av.y;
        As[lcol + 2][lrow] = av.z;
        As[lcol + 3][lrow] = av.w;
        Bs[lcol + 0][lrow] = bv.x;
        Bs[lcol + 1][lrow] = bv.y;
        Bs[lcol + 2][lrow] = bv.z;
        Bs[lcol + 3][lrow] = bv.w;
        __syncthreads();

        #pragma unroll
        for (int k = 0; k < 8; k++) {
            float4 a0 = *(const float4*)&As[k][ty * 4];
            float4 a1 = *(const float4*)&As[k][64 + ty * 4];
            float4 b0 = *(const float4*)&Bs[k][tx * 4];
            float4 b1 = *(const float4*)&Bs[k][64 + tx * 4];
            float af[8] = {a0.x, a0.y, a0.z, a0.w, a1.x, a1.y, a1.z, a1.w};
            float bf[8] = {b0.x, b0.y, b0.z, b0.w, b1.x, b1.y, b1.z, b1.w};
            #pragma unroll
            for (int i = 0; i < 8; i++)
                #pragma unroll
                for (int j = 0; j < 8; j++)
                    acc[i][j] += af[i] * bf[j];
        }
        __syncthreads();
    }

    // epilogue: rows {ty*4..+3, 64+ty*4..+3}, cols {tx*4..+3, 64+tx*4..+3}
    #pragma unroll
    for (int ih = 0; ih < 2; ih++) {
        #pragma unroll
        for (int ii = 0; ii < 4; ii++) {
            const int i = ih * 4 + ii;
            const int r = row0 + ih * 64 + ty * 4 + ii;
            #pragma unroll
            for (int jh = 0; jh < 2; jh++) {
                const int c = col0 + jh * 64 + tx * 4;
                float4 bia = *(const float4*)(bias + c);
                float4 v;
                v.x = acc[i][jh * 4 + 0] + bia.x;
                v.y = acc[i][jh * 4 + 1] + bia.y;
                v.z = acc[i][jh * 4 + 2] + bia.z;
                v.w = acc[i][jh * 4 + 3] + bia.w;
                if (mode == 1) {
                    v.x = fmaxf(v.x, 0.0f); v.y = fmaxf(v.y, 0.0f);
                    v.z = fmaxf(v.z, 0.0f); v.w = fmaxf(v.w, 0.0f);
                } else if (mode == 2) {
                    float4 rv = *(const float4*)(resid + (size_t)r * ldc + c);
                    v.x += rv.x; v.y += rv.y; v.z += rv.z; v.w += rv.w;
                }
                *(float4*)(C + (size_t)r * ldc + c) = v;
            }
        }
    }
}

// ---------------------------------------------------------------------------
// Flash-style attention: per (q-tile of 64, b*h), stream K/V in 64-row tiles
// with online softmax. 256 threads, 4x4 outputs per thread.
// q/k/v are [N, D] with head h at cols [h*64, h*64+64).
// ---------------------------------------------------------------------------
#define TQ 64
#define TK 64
#define SPAD 68   // 64 + 4, keeps float4 alignment, kills bank conflicts

__global__ __launch_bounds__(256) void attn_kernel(
    const float* __restrict__ Q,
    const float* __restrict__ Km,
    const float* __restrict__ Vm,
    float*       __restrict__ O)
{
    extern __shared__ float smem[];
    float* Qs   = smem;                   // TQ * SPAD
    float* KVs  = Qs  + TQ * SPAD;        // TK * SPAD (K, then reused for V)
    float* Ss   = KVs + TK * SPAD;        // TQ * SPAD
    float* mrow = Ss  + TQ * SPAD;        // TQ
    float* lrow = mrow + TQ;              // TQ
    float* crow = lrow + TQ;              // TQ

    const int qb  = blockIdx.x;           // 0..31
    const int bh  = blockIdx.y;           // 0..63
    const int b   = bh >> 4;
    const int h   = bh & 15;
    const int tid = threadIdx.x;
    const int ty  = tid >> 4;
    const int tx  = tid & 15;

    const size_t base = (size_t)b * SS * DD + (size_t)h * DH;
    const int q0 = qb * TQ;

    // load Q tile
    for (int t = tid; t < TQ * (DH / 4); t += 256) {
        const int r  = t >> 4;
        const int d4 = (t & 15) << 2;
        *(float4*)&Qs[r * SPAD + d4] =
            *(const float4*)(Q + base + (size_t)(q0 + r) * DD + d4);
    }
    if (tid < TQ) { mrow[tid] = -1e30f; lrow[tid] = 0.0f; }

    float acc[4][4];
    #pragma unroll
    for (int i = 0; i < 4; i++)
        #pragma unroll
        for (int j = 0; j < 4; j++) acc[i][j] = 0.0f;

    __syncthreads();

    for (int kt = 0; kt < SS / TK; kt++) {
        const int k0 = kt * TK;

        // load K tile
        for (int t = tid; t < TK * (DH / 4); t += 256) {
            const int r  = t >> 4;
            const int d4 = (t & 15) << 2;
            *(float4*)&KVs[r * SPAD + d4] =
                *(const float4*)(Km + base + (size_t)(k0 + r) * DD + d4);
        }
        __syncthreads();

        // scores S = scale * Q K^T  (each thread: 4x4)
        float sreg[4][4];
        #pragma unroll
        for (int i = 0; i < 4; i++)
            #pragma unroll
            for (int j = 0; j < 4; j++) sreg[i][j] = 0.0f;

        #pragma unroll
        for (int d = 0; d < DH; d += 4) {
            float4 q4[4], k4[4];
            #pragma unroll
            for (int i = 0; i < 4; i++)
                q4[i] = *(const float4*)&Qs[(ty + 16 * i) * SPAD + d];
            #pragma unroll
            for (int j = 0; j < 4; j++)
                k4[j] = *(const float4*)&KVs[(tx + 16 * j) * SPAD + d];
            #pragma unroll
            for (int i = 0; i < 4; i++)
                #pragma unroll
                for (int j = 0; j < 4; j++)
                    sreg[i][j] += q4[i].x * k4[j].x + q4[i].y * k4[j].y +
                                  q4[i].z * k4[j].z + q4[i].w * k4[j].w;
        }
        #pragma unroll
        for (int i = 0; i < 4; i++)
            #pragma unroll
            for (int j = 0; j < 4; j++)
                Ss[(ty + 16 * i) * SPAD + tx + 16 * j] = sreg[i][j] * SCALE;
        __syncthreads();

        // online softmax update: 4 lanes per row
        {
            const int r   = tid >> 2;
            const int sub = tid & 3;
            float* srow = &Ss[r * SPAD + sub * 16];
            float mt = -1e30f;
            #pragma unroll
            for (int c = 0; c < 16; c++) mt = fmaxf(mt, srow[c]);
            mt = fmaxf(mt, __shfl_xor_sync(0xffffffff, mt, 1));
            mt = fmaxf(mt, __shfl_xor_sync(0xffffffff, mt, 2));
            const float mold = mrow[r];
            const float mnew = fmaxf(mold, mt);
            float ls = 0.0f;
            #pragma unroll
            for (int c = 0; c < 16; c++) {
                float p = __expf(srow[c] - mnew);
                srow[c] = p;
                ls += p;
            }
            ls += __shfl_xor_sync(0xffffffff, ls, 1);
            ls += __shfl_xor_sync(0xffffffff, ls, 2);
            if (sub == 0) {
                const float corr = __expf(mold - mnew);
                crow[r] = corr;
                lrow[r] = lrow[r] * corr + ls;
                mrow[r] = mnew;
            }
        }
        __syncthreads();

        // rescale acc, then load V (overwriting K buffer)
        float cf[4];
        #pragma unroll
        for (int i = 0; i < 4; i++) cf[i] = crow[ty + 16 * i];
        #pragma unroll
        for (int i = 0; i < 4; i++)
            #pragma unroll
            for (int j = 0; j < 4; j++) acc[i][j] *= cf[i];

        for (int t = tid; t < TK * (DH / 4); t += 256) {
            const int r  = t >> 4;
            const int d4 = (t & 15) << 2;
            *(float4*)&KVs[r * SPAD + d4] =
                *(const float4*)(Vm + base + (size_t)(k0 + r) * DD + d4);
        }
        __syncthreads();

        // acc += P V
        #pragma unroll
        for (int kk = 0; kk < TK; kk += 4) {
            float4 s4[4];
            #pragma unroll
            for (int i = 0; i < 4; i++)
                s4[i] = *(const float4*)&Ss[(ty + 16 * i) * SPAD + kk];
            float vv[4][4];
            #pragma unroll
            for (int t = 0; t < 4; t++)
                #pragma unroll
                for (int j = 0; j < 4; j++)
                    vv[t][j] = KVs[(kk + t) * SPAD + tx + 16 * j];
            #pragma unroll
            for (int i = 0; i < 4; i++)
                #pragma unroll
                for (int j = 0; j < 4; j++)
                    acc[i][j] += s4[i].x * vv[0][j] + s4[i].y * vv[1][j] +
                                 s4[i].z * vv[2][j] + s4[i].w * vv[3][j];
        }
        __syncthreads();   // before next tile overwrites KVs / Ss
    }

    // epilogue: normalize by l and store
    float linv[4];
    #pragma unroll
    for (int i = 0; i < 4; i++) linv[i] = 1.0f / lrow[ty + 16 * i];
    #pragma unroll
    for (int i = 0; i < 4; i++) {
        const int r = q0 + ty + 16 * i;
        #pragma unroll
        for (int j = 0; j < 4; j++) {
            const int c = tx + 16 * j;
            O[base + (size_t)r * DD + c] = acc[i][j] * linv[i];
        }
    }
}

// ---------------------------------------------------------------------------
// launch
// ---------------------------------------------------------------------------
extern "C" void kernel_launch(void* const* d_in, const int* in_sizes, int n_in,
                              void* d_out, int out_size)
{
    const float* x      = (const float*)d_in[0];
    const float* alpha1 = (const float*)d_in[1];
    const float* bias1  = (const float*)d_in[2];
    const float* alpha2 = (const float*)d_in[3];
    const float* bias2  = (const float*)d_in[4];
    const float* wq     = (const float*)d_in[5];
    const float* bq     = (const float*)d_in[6];
    const float* wk     = (const float*)d_in[7];
    const float* bk     = (const float*)d_in[8];
    const float* wv     = (const float*)d_in[9];
    const float* bv     = (const float*)d_in[10];
    const float* w1     = (const float*)d_in[11];
    const float* b1     = (const float*)d_in[12];
    const float* w2     = (const float*)d_in[13];
    const float* b2     = (const float*)d_in[14];
    float* out = (float*)d_out;

    float *p_x2, *p_q, *p_k, *p_v, *p_attn, *p_xres, *p_x2b, *p_h;
    cudaGetSymbolAddress((void**)&p_x2,   g_x2);
    cudaGetSymbolAddress((void**)&p_q,    g_q);
    cudaGetSymbolAddress((void**)&p_k,    g_k);
    cudaGetSymbolAddress((void**)&p_v,    g_v);
    cudaGetSymbolAddress((void**)&p_attn, g_attn);
    cudaGetSymbolAddress((void**)&p_xres, g_xres);
    cudaGetSymbolAddress((void**)&p_x2b,  g_x2b);
    cudaGetSymbolAddress((void**)&p_h,    g_h);

    const int ATTN_SMEM = (3 * TQ * SPAD + 3 * TQ) * (int)sizeof(float);
    cudaFuncSetAttribute(attn_kernel,
                         cudaFuncAttributeMaxDynamicSharedMemorySize, ATTN_SMEM);

    // 1) norm1
    ln_kernel<<<NN, 256>>>(x, nullptr, nullptr, p_x2, alpha1, bias1, 0);

    // 2) q, k, v projections
    dim3 gqkv(DD / 128, NN / 128);
    sgemm_nt<<<gqkv, 256>>>(p_x2, wq, bq, nullptr, p_q, DD, DD, 0);
    sgemm_nt<<<gqkv, 256>>>(p_x2, wk, bk, nullptr, p_k, DD, DD, 0);
    sgemm_nt<<<gqkv, 256>>>(p_x2, wv, bv, nullptr, p_v, DD, DD, 0);

    // 3) attention
    attn_kernel<<<dim3(SS / TQ, BB * HH), 256, ATTN_SMEM>>>(p_q, p_k, p_v, p_attn);

    // 4) residual + norm2 + threshold mask
    ln_kernel<<<NN, 256>>>(x, p_attn, p_xres, p_x2b, alpha2, bias2, 1);

    // 5) ffn1 + relu
    sgemm_nt<<<dim3(FF / 128, NN / 128), 256>>>(p_x2b, w1, b1, nullptr, p_h, DD, FF, 1);

    // 6) ffn2 + bias + residual -> out
    sgemm_nt<<<dim3(DD / 128, NN / 128), 256>>>(p_h, w2, b2, p_xres, out, FF, DD, 2);
}

// round 4
// speedup vs baseline: 1.9903x; 1.9903x over previous
#include <cuda_runtime.h>
#include <cuda_bf16.h>
#include <math.h>
#include <cstdint>

// ---------------------------------------------------------------------------
// Problem constants
// ---------------------------------------------------------------------------
#define BB 4
#define SS 2048
#define DD 1024
#define HH 16
#define DH 64
#define FF 4096
#define NN (BB * SS)          // 8192 rows
#define EPS 1e-6f
#define THRESH 0.15f
#define SCALE 0.125f          // 1/sqrt(64)

// ---------------------------------------------------------------------------
// Scratch (static __device__ arrays; no allocation allowed)
// ---------------------------------------------------------------------------
__device__ float g_x2  [NN * DD];   // norm1(x), tf32-rounded
__device__ float g_q   [NN * DD];
__device__ float g_k   [NN * DD];
__device__ float g_v   [NN * DD];
__device__ float g_attn[NN * DD];
__device__ float g_xres[NN * DD];   // x + attn
__device__ float g_x2b [NN * DD];   // masked norm2(xres), tf32-rounded
__device__ float g_h   [NN * FF];   // relu(ffn1), tf32-rounded
// tf32-rounded weights
__device__ float g_wqr [DD * DD];
__device__ float g_wkr [DD * DD];
__device__ float g_wvr [DD * DD];
__device__ float g_w1r [FF * DD];
__device__ float g_w2r [DD * FF];

// ---------------------------------------------------------------------------
// helpers
// ---------------------------------------------------------------------------
__device__ __forceinline__ uint32_t smem_u32(const void* p) {
    uint32_t a;
    asm("{ .reg .u64 t; cvta.to.shared.u64 t, %1; cvt.u32.u64 %0, t; }"
        : "=r"(a) : "l"(p));
    return a;
}

__device__ __forceinline__ float rna_tf32(float x) {
    uint32_t r;
    asm("cvt.rna.tf32.f32 %0, %1;" : "=r"(r) : "f"(x));
    return __uint_as_float(r);
}

__device__ __forceinline__ void cp16(uint32_t dst, const void* src) {
    asm volatile("cp.async.cg.shared.global [%0], [%1], 16;" :: "r"(dst), "l"(src));
}
#define CP_COMMIT() asm volatile("cp.async.commit_group;" ::: "memory")
#define CP_WAIT1()  asm volatile("cp.async.wait_group 1;" ::: "memory")

__device__ __forceinline__ void mma_tf32(float c[4], const uint32_t a[4],
                                         uint32_t b0, uint32_t b1) {
    asm volatile(
        "mma.sync.aligned.m16n8k8.row.col.f32.tf32.tf32.f32 "
        "{%0,%1,%2,%3}, {%4,%5,%6,%7}, {%8,%9}, {%0,%1,%2,%3};"
        : "+f"(c[0]), "+f"(c[1]), "+f"(c[2]), "+f"(c[3])
        : "r"(a[0]), "r"(a[1]), "r"(a[2]), "r"(a[3]), "r"(b0), "r"(b1));
}

// ---------------------------------------------------------------------------
// tf32 round pass for weights
// ---------------------------------------------------------------------------
__global__ __launch_bounds__(256) void round_tf32_kernel(
    const float* __restrict__ src, float* __restrict__ dst, int n4)
{
    int i = blockIdx.x * 256 + threadIdx.x;
    if (i < n4) {
        float4 v = ((const float4*)src)[i];
        v.x = rna_tf32(v.x); v.y = rna_tf32(v.y);
        v.z = rna_tf32(v.z); v.w = rna_tf32(v.w);
        ((float4*)dst)[i] = v;
    }
}

// ---------------------------------------------------------------------------
// tf32 mma.sync GEMM: C[M,O] = A[M,K] @ W[O,K]^T + bias  (+relu/+resid)
// 128x128 tile, BK=32, 2-stage cp.async, 256 threads (8 warps 4x2).
// mode: 0 = plain, 1 = relu + tf32-round (feeds next GEMM), 2 = add resid
// A and W must already be tf32-rounded values.
// ---------------------------------------------------------------------------
#define MBK  32
#define MBM  128
#define MBN  128
#define APAD 36                         // BK + 4 -> conflict-free frag LDS
#define STAGE_FLOATS (MBM * APAD)       // 4608 floats per matrix per stage
#define GSMEM_BYTES (4 * STAGE_FLOATS * 4)  // A0,A1,B0,B1 = 73728 B

__global__ __launch_bounds__(256, 2) void mma_gemm(
    const float* __restrict__ A,
    const float* __restrict__ W0, const float* __restrict__ W1, const float* __restrict__ W2,
    const float* __restrict__ bi0, const float* __restrict__ bi1, const float* __restrict__ bi2,
    const float* __restrict__ resid,
    float* __restrict__ C0, float* __restrict__ C1, float* __restrict__ C2,
    int K, int ldc, int mode)
{
    extern __shared__ __align__(16) float sm[];
    float* As = sm;                       // [2][STAGE_FLOATS]
    float* Bs = sm + 2 * STAGE_FLOATS;    // [2][STAGE_FLOATS]
    const uint32_t sA = smem_u32(As);
    const uint32_t sB = smem_u32(Bs);

    const float* W    = (blockIdx.z == 0) ? W0  : (blockIdx.z == 1) ? W1  : W2;
    const float* bias = (blockIdx.z == 0) ? bi0 : (blockIdx.z == 1) ? bi1 : bi2;
    float*       C    = (blockIdx.z == 0) ? C0  : (blockIdx.z == 1) ? C1  : C2;

    const int tid    = threadIdx.x;
    const int wid    = tid >> 5;
    const int lane   = tid & 31;
    const int warp_m = wid >> 1;          // 0..3
    const int warp_n = wid & 1;           // 0..1
    const int g      = lane >> 2;         // 0..7
    const int t4     = lane & 3;          // 0..3

    const int row0 = blockIdx.y * MBM;
    const int col0 = blockIdx.x * MBN;

    const float* gA = A + (size_t)row0 * K;
    const float* gW = W + (size_t)col0 * K;

    // per-thread cp.async lanes: 4 chunks each for A and B per stage
    const int lrow0 = tid >> 3;           // 0..31 (x4 groups of 32 rows)
    const int lkc   = (tid & 7) * 4;      // float offset within BK

    float acc[2][8][4];
    #pragma unroll
    for (int mt = 0; mt < 2; mt++)
        #pragma unroll
        for (int nt = 0; nt < 8; nt++)
            #pragma unroll
            for (int j = 0; j < 4; j++) acc[mt][nt][j] = 0.0f;

    const int NT = K / MBK;

    auto load_stage = [&](int buf, int kt) {
        const size_t kof = (size_t)kt * MBK + lkc;
        const uint32_t da = sA + (buf * STAGE_FLOATS) * 4;
        const uint32_t db = sB + (buf * STAGE_FLOATS) * 4;
        #pragma unroll
        for (int i = 0; i < 4; i++) {
            const int row = lrow0 + 32 * i;
            const uint32_t so = (row * APAD + lkc) * 4;
            cp16(da + so, gA + (size_t)row * K + kof);
            cp16(db + so, gW + (size_t)row * K + kof);
        }
    };

    load_stage(0, 0);
    CP_COMMIT();

    const uint32_t* Asu = (const uint32_t*)As;
    const uint32_t* Bsu = (const uint32_t*)Bs;

    for (int t = 0; t < NT; t++) {
        if (t + 1 < NT) load_stage((t + 1) & 1, t + 1);
        CP_COMMIT();
        CP_WAIT1();
        __syncthreads();

        const int buf = t & 1;
        const uint32_t* sa = Asu + buf * STAGE_FLOATS + (warp_m * 32 + g) * APAD + t4;
        const uint32_t* sb = Bsu + buf * STAGE_FLOATS + (warp_n * 64 + g) * APAD + t4;

        #pragma unroll
        for (int ks = 0; ks < 4; ks++) {
            const int k = ks * 8;
            uint32_t a[2][4];
            #pragma unroll
            for (int mt = 0; mt < 2; mt++) {
                const uint32_t* ap = sa + (mt * 16) * APAD + k;
                a[mt][0] = ap[0];
                a[mt][1] = ap[8 * APAD];
                a[mt][2] = ap[4];
                a[mt][3] = ap[8 * APAD + 4];
            }
            #pragma unroll
            for (int nt = 0; nt < 8; nt++) {
                const uint32_t* bp = sb + (nt * 8) * APAD + k;
                const uint32_t b0 = bp[0];
                const uint32_t b1 = bp[4];
                mma_tf32(acc[0][nt], a[0], b0, b1);
                mma_tf32(acc[1][nt], a[1], b0, b1);
            }
        }
        __syncthreads();
    }

    // epilogue
    const int rb = row0 + warp_m * 32 + g;
    const int cb = col0 + warp_n * 64 + t4 * 2;
    #pragma unroll
    for (int mt = 0; mt < 2; mt++) {
        const int r = rb + mt * 16;
        #pragma unroll
        for (int nt = 0; nt < 8; nt++) {
            const int c = cb + nt * 8;
            const float2 bv = *(const float2*)(bias + c);
            float2 v0, v1;
            v0.x = acc[mt][nt][0] + bv.x;
            v0.y = acc[mt][nt][1] + bv.y;
            v1.x = acc[mt][nt][2] + bv.x;
            v1.y = acc[mt][nt][3] + bv.y;
            if (mode == 1) {
                v0.x = rna_tf32(fmaxf(v0.x, 0.0f));
                v0.y = rna_tf32(fmaxf(v0.y, 0.0f));
                v1.x = rna_tf32(fmaxf(v1.x, 0.0f));
                v1.y = rna_tf32(fmaxf(v1.y, 0.0f));
            } else if (mode == 2) {
                const float2 r0 = *(const float2*)(resid + (size_t)r * ldc + c);
                const float2 r1 = *(const float2*)(resid + (size_t)(r + 8) * ldc + c);
                v0.x += r0.x; v0.y += r0.y;
                v1.x += r1.x; v1.y += r1.y;
            }
            *(float2*)(C + (size_t)r * ldc + c)       = v0;
            *(float2*)(C + (size_t)(r + 8) * ldc + c) = v1;
        }
    }
}

// ---------------------------------------------------------------------------
// LayerNorm (+optional residual-in/out, +optional mask); output tf32-rounded
// ---------------------------------------------------------------------------
__global__ __launch_bounds__(256) void ln_kernel(
    const float* __restrict__ x,
    const float* __restrict__ resid,
    float*       __restrict__ out_res,
    float*       __restrict__ out_norm,
    const float* __restrict__ alpha,
    const float* __restrict__ beta,
    int apply_mask)
{
    __shared__ float red[256];
    const int n   = blockIdx.x;
    const int tid = threadIdx.x;
    const size_t off = (size_t)n * DD;
    const int d4 = tid * 4;

    float4 xv = *(const float4*)(x + off + d4);
    if (resid) {
        float4 rv = *(const float4*)(resid + off + d4);
        xv.x += rv.x; xv.y += rv.y; xv.z += rv.z; xv.w += rv.w;
    }
    if (out_res) *(float4*)(out_res + off + d4) = xv;

    float s = xv.x + xv.y + xv.z + xv.w;
    red[tid] = s;
    __syncthreads();
    #pragma unroll
    for (int st = 128; st > 0; st >>= 1) {
        if (tid < st) red[tid] += red[tid + st];
        __syncthreads();
    }
    const float mu = red[0] * (1.0f / DD);
    __syncthreads();

    float dx0 = xv.x - mu, dx1 = xv.y - mu, dx2 = xv.z - mu, dx3 = xv.w - mu;
    red[tid] = dx0*dx0 + dx1*dx1 + dx2*dx2 + dx3*dx3;
    __syncthreads();
    #pragma unroll
    for (int st = 128; st > 0; st >>= 1) {
        if (tid < st) red[tid] += red[tid + st];
        __syncthreads();
    }
    const float var = red[0] * (1.0f / (DD - 1));
    const float inv = 1.0f / (sqrtf(var) + EPS);

    float4 av = *(const float4*)(alpha + d4);
    float4 bv = *(const float4*)(beta  + d4);
    float4 y;
    y.x = av.x * dx0 * inv + bv.x;
    y.y = av.y * dx1 * inv + bv.y;
    y.z = av.z * dx2 * inv + bv.z;
    y.w = av.w * dx3 * inv + bv.w;
    if (apply_mask) {
        if (y.x < THRESH) y.x = 0.0f;
        if (y.y < THRESH) y.y = 0.0f;
        if (y.z < THRESH) y.z = 0.0f;
        if (y.w < THRESH) y.w = 0.0f;
    }
    // tf32-round: consumed by mma GEMMs
    y.x = rna_tf32(y.x); y.y = rna_tf32(y.y);
    y.z = rna_tf32(y.z); y.w = rna_tf32(y.w);
    *(float4*)(out_norm + off + d4) = y;
}

// ---------------------------------------------------------------------------
// Flash-style SIMT attention — unchanged
// ---------------------------------------------------------------------------
#define TQ 64
#define TK 64
#define SPAD 68

__global__ __launch_bounds__(256) void attn_kernel(
    const float* __restrict__ Q,
    const float* __restrict__ Km,
    const float* __restrict__ Vm,
    float*       __restrict__ O)
{
    extern __shared__ float fsm[];
    float* Qs   = fsm;
    float* KVs  = Qs  + TQ * SPAD;
    float* Ss   = KVs + TK * SPAD;
    float* mrow = Ss  + TQ * SPAD;
    float* lrow = mrow + TQ;
    float* crow = lrow + TQ;

    const int qb  = blockIdx.x;
    const int bh  = blockIdx.y;
    const int b   = bh >> 4;
    const int h   = bh & 15;
    const int tid = threadIdx.x;
    const int ty  = tid >> 4;
    const int tx  = tid & 15;

    const size_t base = (size_t)b * SS * DD + (size_t)h * DH;
    const int q0 = qb * TQ;

    for (int t = tid; t < TQ * (DH / 4); t += 256) {
        const int r  = t >> 4;
        const int d4 = (t & 15) << 2;
        *(float4*)&Qs[r * SPAD + d4] =
            *(const float4*)(Q + base + (size_t)(q0 + r) * DD + d4);
    }
    if (tid < TQ) { mrow[tid] = -1e30f; lrow[tid] = 0.0f; }

    float acc[4][4];
    #pragma unroll
    for (int i = 0; i < 4; i++)
        #pragma unroll
        for (int j = 0; j < 4; j++) acc[i][j] = 0.0f;

    __syncthreads();

    for (int kt = 0; kt < SS / TK; kt++) {
        const int k0 = kt * TK;

        for (int t = tid; t < TK * (DH / 4); t += 256) {
            const int r  = t >> 4;
            const int d4 = (t & 15) << 2;
            *(float4*)&KVs[r * SPAD + d4] =
                *(const float4*)(Km + base + (size_t)(k0 + r) * DD + d4);
        }
        __syncthreads();

        float sreg[4][4];
        #pragma unroll
        for (int i = 0; i < 4; i++)
            #pragma unroll
            for (int j = 0; j < 4; j++) sreg[i][j] = 0.0f;

        #pragma unroll
        for (int d = 0; d < DH; d += 4) {
            float4 q4[4], k4[4];
            #pragma unroll
            for (int i = 0; i < 4; i++)
                q4[i] = *(const float4*)&Qs[(ty + 16 * i) * SPAD + d];
            #pragma unroll
            for (int j = 0; j < 4; j++)
                k4[j] = *(const float4*)&KVs[(tx + 16 * j) * SPAD + d];
            #pragma unroll
            for (int i = 0; i < 4; i++)
                #pragma unroll
                for (int j = 0; j < 4; j++)
                    sreg[i][j] += q4[i].x * k4[j].x + q4[i].y * k4[j].y +
                                  q4[i].z * k4[j].z + q4[i].w * k4[j].w;
        }
        #pragma unroll
        for (int i = 0; i < 4; i++)
            #pragma unroll
            for (int j = 0; j < 4; j++)
                Ss[(ty + 16 * i) * SPAD + tx + 16 * j] = sreg[i][j] * SCALE;
        __syncthreads();

        {
            const int r   = tid >> 2;
            const int sub = tid & 3;
            float* srow = &Ss[r * SPAD + sub * 16];
            float mt = -1e30f;
            #pragma unroll
            for (int c = 0; c < 16; c++) mt = fmaxf(mt, srow[c]);
            mt = fmaxf(mt, __shfl_xor_sync(0xffffffff, mt, 1));
            mt = fmaxf(mt, __shfl_xor_sync(0xffffffff, mt, 2));
            const float mold = mrow[r];
            const float mnew = fmaxf(mold, mt);
            float ls = 0.0f;
            #pragma unroll
            for (int c = 0; c < 16; c++) {
                float p = __expf(srow[c] - mnew);
                srow[c] = p;
                ls += p;
            }
            ls += __shfl_xor_sync(0xffffffff, ls, 1);
            ls += __shfl_xor_sync(0xffffffff, ls, 2);
            if (sub == 0) {
                const float corr = __expf(mold - mnew);
                crow[r] = corr;
                lrow[r] = lrow[r] * corr + ls;
                mrow[r] = mnew;
            }
        }
        __syncthreads();

        float cf[4];
        #pragma unroll
        for (int i = 0; i < 4; i++) cf[i] = crow[ty + 16 * i];
        #pragma unroll
        for (int i = 0; i < 4; i++)
            #pragma unroll
            for (int j = 0; j < 4; j++) acc[i][j] *= cf[i];

        for (int t = tid; t < TK * (DH / 4); t += 256) {
            const int r  = t >> 4;
            const int d4 = (t & 15) << 2;
            *(float4*)&KVs[r * SPAD + d4] =
                *(const float4*)(Vm + base + (size_t)(k0 + r) * DD + d4);
        }
        __syncthreads();

        #pragma unroll
        for (int kk = 0; kk < TK; kk += 4) {
            float4 s4[4];
            #pragma unroll
            for (int i = 0; i < 4; i++)
                s4[i] = *(const float4*)&Ss[(ty + 16 * i) * SPAD + kk];
            float vv[4][4];
            #pragma unroll
            for (int t = 0; t < 4; t++)
                #pragma unroll
                for (int j = 0; j < 4; j++)
                    vv[t][j] = KVs[(kk + t) * SPAD + tx + 16 * j];
            #pragma unroll
            for (int i = 0; i < 4; i++)
                #pragma unroll
                for (int j = 0; j < 4; j++)
                    acc[i][j] += s4[i].x * vv[0][j] + s4[i].y * vv[1][j] +
                                 s4[i].z * vv[2][j] + s4[i].w * vv[3][j];
        }
        __syncthreads();
    }

    float linv[4];
    #pragma unroll
    for (int i = 0; i < 4; i++) linv[i] = 1.0f / lrow[ty + 16 * i];
    #pragma unroll
    for (int i = 0; i < 4; i++) {
        const int r = q0 + ty + 16 * i;
        #pragma unroll
        for (int j = 0; j < 4; j++) {
            const int c = tx + 16 * j;
            O[base + (size_t)r * DD + c] = acc[i][j] * linv[i];
        }
    }
}

// ---------------------------------------------------------------------------
// launch
// ---------------------------------------------------------------------------
extern "C" void kernel_launch(void* const* d_in, const int* in_sizes, int n_in,
                              void* d_out, int out_size)
{
    const float* x      = (const float*)d_in[0];
    const float* alpha1 = (const float*)d_in[1];
    const float* bias1  = (const float*)d_in[2];
    const float* alpha2 = (const float*)d_in[3];
    const float* bias2  = (const float*)d_in[4];
    const float* wq     = (const float*)d_in[5];
    const float* bq     = (const float*)d_in[6];
    const float* wk     = (const float*)d_in[7];
    const float* bk     = (const float*)d_in[8];
    const float* wv     = (const float*)d_in[9];
    const float* bv     = (const float*)d_in[10];
    const float* w1     = (const float*)d_in[11];
    const float* b1     = (const float*)d_in[12];
    const float* w2     = (const float*)d_in[13];
    const float* b2     = (const float*)d_in[14];
    float* out = (float*)d_out;

    float *p_x2, *p_q, *p_k, *p_v, *p_attn, *p_xres, *p_x2b, *p_h;
    float *p_wqr, *p_wkr, *p_wvr, *p_w1r, *p_w2r;
    cudaGetSymbolAddress((void**)&p_x2,   g_x2);
    cudaGetSymbolAddress((void**)&p_q,    g_q);
    cudaGetSymbolAddress((void**)&p_k,    g_k);
    cudaGetSymbolAddress((void**)&p_v,    g_v);
    cudaGetSymbolAddress((void**)&p_attn, g_attn);
    cudaGetSymbolAddress((void**)&p_xres, g_xres);
    cudaGetSymbolAddress((void**)&p_x2b,  g_x2b);
    cudaGetSymbolAddress((void**)&p_h,    g_h);
    cudaGetSymbolAddress((void**)&p_wqr,  g_wqr);
    cudaGetSymbolAddress((void**)&p_wkr,  g_wkr);
    cudaGetSymbolAddress((void**)&p_wvr,  g_wvr);
    cudaGetSymbolAddress((void**)&p_w1r,  g_w1r);
    cudaGetSymbolAddress((void**)&p_w2r,  g_w2r);

    const int ATTN_SMEM = (3 * TQ * SPAD + 3 * TQ) * (int)sizeof(float);
    cudaFuncSetAttribute(attn_kernel,
                         cudaFuncAttributeMaxDynamicSharedMemorySize, ATTN_SMEM);
    cudaFuncSetAttribute(mma_gemm,
                         cudaFuncAttributeMaxDynamicSharedMemorySize, GSMEM_BYTES);

    // 0) tf32-round weights
    const int nqkv4 = DD * DD / 4, nff4 = FF * DD / 4;
    round_tf32_kernel<<<(nqkv4 + 255) / 256, 256>>>(wq, p_wqr, nqkv4);
    round_tf32_kernel<<<(nqkv4 + 255) / 256, 256>>>(wk, p_wkr, nqkv4);
    round_tf32_kernel<<<(nqkv4 + 255) / 256, 256>>>(wv, p_wvr, nqkv4);
    round_tf32_kernel<<<(nff4  + 255) / 256, 256>>>(w1, p_w1r, nff4);
    round_tf32_kernel<<<(nff4  + 255) / 256, 256>>>(w2, p_w2r, nff4);

    // 1) norm1 (tf32-rounded out)
    ln_kernel<<<NN, 256>>>(x, nullptr, nullptr, p_x2, alpha1, bias1, 0);

    // 2) fused q,k,v projections (tf32 mma)
    mma_gemm<<<dim3(DD / MBN, NN / MBM, 3), 256, GSMEM_BYTES>>>(
        p_x2, p_wqr, p_wkr, p_wvr, bq, bk, bv, nullptr, p_q, p_k, p_v, DD, DD, 0);

    // 3) attention
    attn_kernel<<<dim3(SS / TQ, BB * HH), 256, ATTN_SMEM>>>(p_q, p_k, p_v, p_attn);

    // 4) residual + norm2 + threshold mask (tf32-rounded out)
    ln_kernel<<<NN, 256>>>(x, p_attn, p_xres, p_x2b, alpha2, bias2, 1);

    // 5) ffn1 + relu (tf32-rounded out)
    mma_gemm<<<dim3(FF / MBN, NN / MBM, 1), 256, GSMEM_BYTES>>>(
        p_x2b, p_w1r, p_w1r, p_w1r, b1, b1, b1, nullptr, p_h, p_h, p_h, DD, FF, 1);

    // 6) ffn2 + bias + residual -> out
    mma_gemm<<<dim3(DD / MBN, NN / MBM, 1), 256, GSMEM_BYTES>>>(
        p_h, p_w2r, p_w2r, p_w2r, b2, b2, b2, p_xres, out, out, out, FF, DD, 2);
}

// round 5
// speedup vs baseline: 3.4425x; 1.7296x over previous
#include <cuda_runtime.h>
#include <cuda_bf16.h>
#include <math.h>
#include <cstdint>

// ---------------------------------------------------------------------------
// Problem constants
// ---------------------------------------------------------------------------
#define BB 4
#define SS 2048
#define DD 1024
#define HH 16
#define DH 64
#define FF 4096
#define NN (BB * SS)
#define EPS 1e-6f
#define THRESH 0.15f
#define SCALE 0.125f

// ---------------------------------------------------------------------------
// Scratch
// ---------------------------------------------------------------------------
__device__ float g_x2  [NN * DD];
__device__ float g_q   [NN * DD];
__device__ float g_k   [NN * DD];
__device__ float g_v   [NN * DD];
__device__ float g_attn[NN * DD];
__device__ float g_xres[NN * DD];
__device__ float g_x2b [NN * DD];
__device__ float g_h   [NN * FF];
__device__ float g_wqr [DD * DD];
__device__ float g_wkr [DD * DD];
__device__ float g_wvr [DD * DD];
__device__ float g_w1r [FF * DD];
__device__ float g_w2r [DD * FF];

// ---------------------------------------------------------------------------
// helpers
// ---------------------------------------------------------------------------
__device__ __forceinline__ uint32_t smem_u32(const void* p) {
    uint32_t a;
    asm("{ .reg .u64 t; cvta.to.shared.u64 t, %1; cvt.u32.u64 %0, t; }"
        : "=r"(a) : "l"(p));
    return a;
}

__device__ __forceinline__ float rna_tf32(float x) {
    uint32_t r;
    asm("cvt.rna.tf32.f32 %0, %1;" : "=r"(r) : "f"(x));
    return __uint_as_float(r);
}

__device__ __forceinline__ void cp16(uint32_t dst, const void* src) {
    asm volatile("cp.async.cg.shared.global [%0], [%1], 16;" :: "r"(dst), "l"(src));
}
#define CP_COMMIT() asm volatile("cp.async.commit_group;" ::: "memory")
#define CP_WAIT0()  asm volatile("cp.async.wait_group 0;" ::: "memory")
#define CP_WAIT1()  asm volatile("cp.async.wait_group 1;" ::: "memory")

__device__ __forceinline__ void mma_tf32(float c[4], const uint32_t a[4],
                                         uint32_t b0, uint32_t b1) {
    asm volatile(
        "mma.sync.aligned.m16n8k8.row.col.f32.tf32.tf32.f32 "
        "{%0,%1,%2,%3}, {%4,%5,%6,%7}, {%8,%9}, {%0,%1,%2,%3};"
        : "+f"(c[0]), "+f"(c[1]), "+f"(c[2]), "+f"(c[3])
        : "r"(a[0]), "r"(a[1]), "r"(a[2]), "r"(a[3]), "r"(b0), "r"(b1));
}

// ---------------------------------------------------------------------------
// tf32 round pass for weights
// ---------------------------------------------------------------------------
__global__ __launch_bounds__(256) void round_tf32_kernel(
    const float* __restrict__ src, float* __restrict__ dst, int n4)
{
    int i = blockIdx.x * 256 + threadIdx.x;
    if (i < n4) {
        float4 v = ((const float4*)src)[i];
        v.x = rna_tf32(v.x); v.y = rna_tf32(v.y);
        v.z = rna_tf32(v.z); v.w = rna_tf32(v.w);
        ((float4*)dst)[i] = v;
    }
}

// ---------------------------------------------------------------------------
// tf32 mma.sync GEMM (same as R4; mode 0 now tf32-rounds output for attention)
// ---------------------------------------------------------------------------
#define MBK  32
#define MBM  128
#define MBN  128
#define APAD 36
#define STAGE_FLOATS (MBM * APAD)
#define GSMEM_BYTES (4 * STAGE_FLOATS * 4)

__global__ __launch_bounds__(256, 2) void mma_gemm(
    const float* __restrict__ A,
    const float* __restrict__ W0, const float* __restrict__ W1, const float* __restrict__ W2,
    const float* __restrict__ bi0, const float* __restrict__ bi1, const float* __restrict__ bi2,
    const float* __restrict__ resid,
    float* __restrict__ C0, float* __restrict__ C1, float* __restrict__ C2,
    int K, int ldc, int mode)
{
    extern __shared__ __align__(16) float sm[];
    float* As = sm;
    float* Bs = sm + 2 * STAGE_FLOATS;
    const uint32_t sA = smem_u32(As);
    const uint32_t sB = smem_u32(Bs);

    const float* W    = (blockIdx.z == 0) ? W0  : (blockIdx.z == 1) ? W1  : W2;
    const float* bias = (blockIdx.z == 0) ? bi0 : (blockIdx.z == 1) ? bi1 : bi2;
    float*       C    = (blockIdx.z == 0) ? C0  : (blockIdx.z == 1) ? C1  : C2;

    const int tid    = threadIdx.x;
    const int wid    = tid >> 5;
    const int lane   = tid & 31;
    const int warp_m = wid >> 1;
    const int warp_n = wid & 1;
    const int g      = lane >> 2;
    const int t4     = lane & 3;

    const int row0 = blockIdx.y * MBM;
    const int col0 = blockIdx.x * MBN;

    const float* gA = A + (size_t)row0 * K;
    const float* gW = W + (size_t)col0 * K;

    const int lrow0 = tid >> 3;
    const int lkc   = (tid & 7) * 4;

    float acc[2][8][4];
    #pragma unroll
    for (int mt = 0; mt < 2; mt++)
        #pragma unroll
        for (int nt = 0; nt < 8; nt++)
            #pragma unroll
            for (int j = 0; j < 4; j++) acc[mt][nt][j] = 0.0f;

    const int NT = K / MBK;

    auto load_stage = [&](int buf, int kt) {
        const size_t kof = (size_t)kt * MBK + lkc;
        const uint32_t da = sA + (buf * STAGE_FLOATS) * 4;
        const uint32_t db = sB + (buf * STAGE_FLOATS) * 4;
        #pragma unroll
        for (int i = 0; i < 4; i++) {
            const int row = lrow0 + 32 * i;
            const uint32_t so = (row * APAD + lkc) * 4;
            cp16(da + so, gA + (size_t)row * K + kof);
            cp16(db + so, gW + (size_t)row * K + kof);
        }
    };

    load_stage(0, 0);
    CP_COMMIT();

    const uint32_t* Asu = (const uint32_t*)As;
    const uint32_t* Bsu = (const uint32_t*)Bs;

    for (int t = 0; t < NT; t++) {
        if (t + 1 < NT) load_stage((t + 1) & 1, t + 1);
        CP_COMMIT();
        CP_WAIT1();
        __syncthreads();

        const int buf = t & 1;
        const uint32_t* sa = Asu + buf * STAGE_FLOATS + (warp_m * 32 + g) * APAD + t4;
        const uint32_t* sb = Bsu + buf * STAGE_FLOATS + (warp_n * 64 + g) * APAD + t4;

        #pragma unroll
        for (int ks = 0; ks < 4; ks++) {
            const int k = ks * 8;
            uint32_t a[2][4];
            #pragma unroll
            for (int mt = 0; mt < 2; mt++) {
                const uint32_t* ap = sa + (mt * 16) * APAD + k;
                a[mt][0] = ap[0];
                a[mt][1] = ap[8 * APAD];
                a[mt][2] = ap[4];
                a[mt][3] = ap[8 * APAD + 4];
            }
            #pragma unroll
            for (int nt = 0; nt < 8; nt++) {
                const uint32_t* bp = sb + (nt * 8) * APAD + k;
                const uint32_t b0 = bp[0];
                const uint32_t b1 = bp[4];
                mma_tf32(acc[0][nt], a[0], b0, b1);
                mma_tf32(acc[1][nt], a[1], b0, b1);
            }
        }
        __syncthreads();
    }

    const int rb = row0 + warp_m * 32 + g;
    const int cb = col0 + warp_n * 64 + t4 * 2;
    #pragma unroll
    for (int mt = 0; mt < 2; mt++) {
        const int r = rb + mt * 16;
        #pragma unroll
        for (int nt = 0; nt < 8; nt++) {
            const int c = cb + nt * 8;
            const float2 bv = *(const float2*)(bias + c);
            float2 v0, v1;
            v0.x = acc[mt][nt][0] + bv.x;
            v0.y = acc[mt][nt][1] + bv.y;
            v1.x = acc[mt][nt][2] + bv.x;
            v1.y = acc[mt][nt][3] + bv.y;
            if (mode == 0) {
                v0.x = rna_tf32(v0.x); v0.y = rna_tf32(v0.y);
                v1.x = rna_tf32(v1.x); v1.y = rna_tf32(v1.y);
            } else if (mode == 1) {
                v0.x = rna_tf32(fmaxf(v0.x, 0.0f));
                v0.y = rna_tf32(fmaxf(v0.y, 0.0f));
                v1.x = rna_tf32(fmaxf(v1.x, 0.0f));
                v1.y = rna_tf32(fmaxf(v1.y, 0.0f));
            } else if (mode == 2) {
                const float2 r0 = *(const float2*)(resid + (size_t)r * ldc + c);
                const float2 r1 = *(const float2*)(resid + (size_t)(r + 8) * ldc + c);
                v0.x += r0.x; v0.y += r0.y;
                v1.x += r1.x; v1.y += r1.y;
            }
            *(float2*)(C + (size_t)r * ldc + c)       = v0;
            *(float2*)(C + (size_t)(r + 8) * ldc + c) = v1;
        }
    }
}

// ---------------------------------------------------------------------------
// LayerNorm — output tf32-rounded
// ---------------------------------------------------------------------------
__global__ __launch_bounds__(256) void ln_kernel(
    const float* __restrict__ x,
    const float* __restrict__ resid,
    float*       __restrict__ out_res,
    float*       __restrict__ out_norm,
    const float* __restrict__ alpha,
    const float* __restrict__ beta,
    int apply_mask)
{
    __shared__ float red[256];
    const int n   = blockIdx.x;
    const int tid = threadIdx.x;
    const size_t off = (size_t)n * DD;
    const int d4 = tid * 4;

    float4 xv = *(const float4*)(x + off + d4);
    if (resid) {
        float4 rv = *(const float4*)(resid + off + d4);
        xv.x += rv.x; xv.y += rv.y; xv.z += rv.z; xv.w += rv.w;
    }
    if (out_res) *(float4*)(out_res + off + d4) = xv;

    float s = xv.x + xv.y + xv.z + xv.w;
    red[tid] = s;
    __syncthreads();
    #pragma unroll
    for (int st = 128; st > 0; st >>= 1) {
        if (tid < st) red[tid] += red[tid + st];
        __syncthreads();
    }
    const float mu = red[0] * (1.0f / DD);
    __syncthreads();

    float dx0 = xv.x - mu, dx1 = xv.y - mu, dx2 = xv.z - mu, dx3 = xv.w - mu;
    red[tid] = dx0*dx0 + dx1*dx1 + dx2*dx2 + dx3*dx3;
    __syncthreads();
    #pragma unroll
    for (int st = 128; st > 0; st >>= 1) {
        if (tid < st) red[tid] += red[tid + st];
        __syncthreads();
    }
    const float var = red[0] * (1.0f / (DD - 1));
    const float inv = 1.0f / (sqrtf(var) + EPS);

    float4 av = *(const float4*)(alpha + d4);
    float4 bv = *(const float4*)(beta  + d4);
    float4 y;
    y.x = av.x * dx0 * inv + bv.x;
    y.y = av.y * dx1 * inv + bv.y;
    y.z = av.z * dx2 * inv + bv.z;
    y.w = av.w * dx3 * inv + bv.w;
    if (apply_mask) {
        if (y.x < THRESH) y.x = 0.0f;
        if (y.y < THRESH) y.y = 0.0f;
        if (y.z < THRESH) y.z = 0.0f;
        if (y.w < THRESH) y.w = 0.0f;
    }
    y.x = rna_tf32(y.x); y.y = rna_tf32(y.y);
    y.z = rna_tf32(y.z); y.w = rna_tf32(y.w);
    *(float4*)(out_norm + off + d4) = y;
}

// ---------------------------------------------------------------------------
// Tensor-core flash attention (tf32 mma.sync)
// 64 q-rows per block, 64-key tiles, 256 threads = 8 warps (4x2).
// Qs/Ks/Ss stride 68 (conflict-free A/B frags), Vs stride 72 (conflict-free
// B frags for PV since V stays [key][d] row-major = col-major B operand).
// ---------------------------------------------------------------------------
#define AST 68
#define VST 72
#define ATTN_SMEM_FLOATS (3 * 64 * AST + 64 * VST + 3 * 64)
#define ATTN_SMEM_BYTES  (ATTN_SMEM_FLOATS * 4)

__global__ __launch_bounds__(256, 2) void attn_mma(
    const float* __restrict__ Q,
    const float* __restrict__ Km,
    const float* __restrict__ Vm,
    float*       __restrict__ O)
{
    extern __shared__ __align__(16) float fsm[];
    float* Qs   = fsm;                    // 64 * AST
    float* Ks   = Qs + 64 * AST;          // 64 * AST
    float* Vs   = Ks + 64 * AST;          // 64 * VST
    float* Ss   = Vs + 64 * VST;          // 64 * AST
    float* mrow = Ss + 64 * AST;
    float* lrow = mrow + 64;
    float* crow = lrow + 64;
    const uint32_t sKu = smem_u32(Ks);
    const uint32_t sVu = smem_u32(Vs);

    const int qb  = blockIdx.x;
    const int bh  = blockIdx.y;
    const int b   = bh >> 4;
    const int h   = bh & 15;
    const int tid = threadIdx.x;
    const int wid    = tid >> 5;
    const int lane   = tid & 31;
    const int warp_m = wid >> 1;          // 0..3
    const int warp_n = wid & 1;           // 0..1
    const int g      = lane >> 2;         // 0..7
    const int t4     = lane & 3;          // 0..3

    const size_t base = (size_t)b * SS * DD + (size_t)h * DH;
    const int q0 = qb * 64;

    // load Q tile (64 x 64)
    {
        const int r  = tid >> 2;
        const int d4 = (tid & 3) << 4;    // 4 float4 chunks per row pair? no:
    }
    for (int t = tid; t < 64 * 16; t += 256) {
        const int r  = t >> 4;
        const int d4 = (t & 15) << 2;
        *(float4*)&Qs[r * AST + d4] =
            *(const float4*)(Q + base + (size_t)(q0 + r) * DD + d4);
    }
    if (tid < 64) { mrow[tid] = -1e30f; lrow[tid] = 0.0f; }

    float acc_o[4][4];
    #pragma unroll
    for (int nt = 0; nt < 4; nt++)
        #pragma unroll
        for (int j = 0; j < 4; j++) acc_o[nt][j] = 0.0f;

    // cp.async lanes for K/V: 4 rows each (16 float4 per row)
    const int lr = tid >> 4;              // 0..15
    const int lc = (tid & 15) << 2;       // float offset

    __syncthreads();

    const uint32_t* Qsu = (const uint32_t*)Qs;
    const uint32_t* Ksu = (const uint32_t*)Ks;
    const uint32_t* Vsu = (const uint32_t*)Vs;
    const uint32_t* Ssu = (const uint32_t*)Ss;

    for (int kt = 0; kt < SS / 64; kt++) {
        const int k0 = kt * 64;

        // load K, V tiles via cp.async
        #pragma unroll
        for (int i = 0; i < 4; i++) {
            const int r = lr + 16 * i;
            const float* kg = Km + base + (size_t)(k0 + r) * DD + lc;
            const float* vg = Vm + base + (size_t)(k0 + r) * DD + lc;
            cp16(sKu + (r * AST + lc) * 4, kg);
            cp16(sVu + (r * VST + lc) * 4, vg);
        }
        CP_COMMIT();
        CP_WAIT0();
        __syncthreads();

        // --- S = scale * Q K^T ---
        float accs[4][4];
        #pragma unroll
        for (int nt = 0; nt < 4; nt++)
            #pragma unroll
            for (int j = 0; j < 4; j++) accs[nt][j] = 0.0f;

        const uint32_t* sa = Qsu + (warp_m * 16 + g) * AST + t4;
        const uint32_t* sb = Ksu + (warp_n * 32 + g) * AST + t4;
        #pragma unroll
        for (int ks = 0; ks < 8; ks++) {
            const int k = ks * 8;
            uint32_t a[4];
            a[0] = sa[k];
            a[1] = sa[8 * AST + k];
            a[2] = sa[k + 4];
            a[3] = sa[8 * AST + k + 4];
            #pragma unroll
            for (int nt = 0; nt < 4; nt++) {
                const uint32_t* bp = sb + (nt * 8) * AST + k;
                mma_tf32(accs[nt], a, bp[0], bp[4]);
            }
        }

        // store S*scale to Ss (accumulator layout)
        {
            const int r0 = warp_m * 16 + g;
            const int c0 = warp_n * 32 + 2 * t4;
            #pragma unroll
            for (int nt = 0; nt < 4; nt++) {
                const int c = c0 + nt * 8;
                float2 lo, hi;
                lo.x = accs[nt][0] * SCALE; lo.y = accs[nt][1] * SCALE;
                hi.x = accs[nt][2] * SCALE; hi.y = accs[nt][3] * SCALE;
                *(float2*)&Ss[r0 * AST + c]       = lo;
                *(float2*)&Ss[(r0 + 8) * AST + c] = hi;
            }
        }
        __syncthreads();

        // --- online softmax (row-wise, 4 threads per row) ---
        {
            const int r   = tid >> 2;
            const int sub = tid & 3;
            float* srow = &Ss[r * AST + sub * 16];
            float mt = -1e30f;
            #pragma unroll
            for (int c = 0; c < 16; c++) mt = fmaxf(mt, srow[c]);
            mt = fmaxf(mt, __shfl_xor_sync(0xffffffff, mt, 1));
            mt = fmaxf(mt, __shfl_xor_sync(0xffffffff, mt, 2));
            const float mold = mrow[r];
            const float mnew = fmaxf(mold, mt);
            float ls = 0.0f;
            #pragma unroll
            for (int c = 0; c < 16; c++) {
                float p = rna_tf32(__expf(srow[c] - mnew));
                srow[c] = p;
                ls += p;
            }
            ls += __shfl_xor_sync(0xffffffff, ls, 1);
            ls += __shfl_xor_sync(0xffffffff, ls, 2);
            if (sub == 0) {
                const float corr = __expf(mold - mnew);
                crow[r] = corr;
                lrow[r] = lrow[r] * corr + ls;
                mrow[r] = mnew;
            }
        }
        __syncthreads();

        // rescale existing accumulator
        {
            const float cf0 = crow[warp_m * 16 + g];
            const float cf1 = crow[warp_m * 16 + g + 8];
            #pragma unroll
            for (int nt = 0; nt < 4; nt++) {
                acc_o[nt][0] *= cf0; acc_o[nt][1] *= cf0;
                acc_o[nt][2] *= cf1; acc_o[nt][3] *= cf1;
            }
        }

        // --- acc_o += P V ---
        {
            const uint32_t* pa = Ssu + (warp_m * 16 + g) * AST + t4;
            const uint32_t* pb = Vsu + t4 * VST + warp_n * 32 + g;
            #pragma unroll
            for (int ks = 0; ks < 8; ks++) {
                const int k = ks * 8;
                uint32_t a[4];
                a[0] = pa[k];
                a[1] = pa[8 * AST + k];
                a[2] = pa[k + 4];
                a[3] = pa[8 * AST + k + 4];
                const uint32_t* bp = pb + ks * 8 * VST;
                #pragma unroll
                for (int nt = 0; nt < 4; nt++) {
                    mma_tf32(acc_o[nt], a, bp[nt * 8], bp[4 * VST + nt * 8]);
                }
            }
        }
        __syncthreads();   // before next tile overwrites Ks/Vs/Ss
    }

    // epilogue: divide by l, store
    {
        const int r0 = warp_m * 16 + g;
        const float li0 = 1.0f / lrow[r0];
        const float li1 = 1.0f / lrow[r0 + 8];
        const size_t ro0 = base + (size_t)(q0 + r0) * DD;
        const size_t ro1 = base + (size_t)(q0 + r0 + 8) * DD;
        const int c0 = warp_n * 32 + 2 * t4;
        #pragma unroll
        for (int nt = 0; nt < 4; nt++) {
            const int c = c0 + nt * 8;
            float2 lo, hi;
            lo.x = acc_o[nt][0] * li0; lo.y = acc_o[nt][1] * li0;
            hi.x = acc_o[nt][2] * li1; hi.y = acc_o[nt][3] * li1;
            *(float2*)(O + ro0 + c) = lo;
            *(float2*)(O + ro1 + c) = hi;
        }
    }
}

// ---------------------------------------------------------------------------
// launch
// ---------------------------------------------------------------------------
extern "C" void kernel_launch(void* const* d_in, const int* in_sizes, int n_in,
                              void* d_out, int out_size)
{
    const float* x      = (const float*)d_in[0];
    const float* alpha1 = (const float*)d_in[1];
    const float* bias1  = (const float*)d_in[2];
    const float* alpha2 = (const float*)d_in[3];
    const float* bias2  = (const float*)d_in[4];
    const float* wq     = (const float*)d_in[5];
    const float* bq     = (const float*)d_in[6];
    const float* wk     = (const float*)d_in[7];
    const float* bk     = (const float*)d_in[8];
    const float* wv     = (const float*)d_in[9];
    const float* bv     = (const float*)d_in[10];
    const float* w1     = (const float*)d_in[11];
    const float* b1     = (const float*)d_in[12];
    const float* w2     = (const float*)d_in[13];
    const float* b2     = (const float*)d_in[14];
    float* out = (float*)d_out;

    float *p_x2, *p_q, *p_k, *p_v, *p_attn, *p_xres, *p_x2b, *p_h;
    float *p_wqr, *p_wkr, *p_wvr, *p_w1r, *p_w2r;
    cudaGetSymbolAddress((void**)&p_x2,   g_x2);
    cudaGetSymbolAddress((void**)&p_q,    g_q);
    cudaGetSymbolAddress((void**)&p_k,    g_k);
    cudaGetSymbolAddress((void**)&p_v,    g_v);
    cudaGetSymbolAddress((void**)&p_attn, g_attn);
    cudaGetSymbolAddress((void**)&p_xres, g_xres);
    cudaGetSymbolAddress((void**)&p_x2b,  g_x2b);
    cudaGetSymbolAddress((void**)&p_h,    g_h);
    cudaGetSymbolAddress((void**)&p_wqr,  g_wqr);
    cudaGetSymbolAddress((void**)&p_wkr,  g_wkr);
    cudaGetSymbolAddress((void**)&p_wvr,  g_wvr);
    cudaGetSymbolAddress((void**)&p_w1r,  g_w1r);
    cudaGetSymbolAddress((void**)&p_w2r,  g_w2r);

    cudaFuncSetAttribute(attn_mma,
                         cudaFuncAttributeMaxDynamicSharedMemorySize, ATTN_SMEM_BYTES);
    cudaFuncSetAttribute(mma_gemm,
                         cudaFuncAttributeMaxDynamicSharedMemorySize, GSMEM_BYTES);

    // 0) tf32-round weights
    const int nqkv4 = DD * DD / 4, nff4 = FF * DD / 4;
    round_tf32_kernel<<<(nqkv4 + 255) / 256, 256>>>(wq, p_wqr, nqkv4);
    round_tf32_kernel<<<(nqkv4 + 255) / 256, 256>>>(wk, p_wkr, nqkv4);
    round_tf32_kernel<<<(nqkv4 + 255) / 256, 256>>>(wv, p_wvr, nqkv4);
    round_tf32_kernel<<<(nff4  + 255) / 256, 256>>>(w1, p_w1r, nff4);
    round_tf32_kernel<<<(nff4  + 255) / 256, 256>>>(w2, p_w2r, nff4);

    // 1) norm1
    ln_kernel<<<NN, 256>>>(x, nullptr, nullptr, p_x2, alpha1, bias1, 0);

    // 2) fused q,k,v projections (outputs tf32-rounded)
    mma_gemm<<<dim3(DD / MBN, NN / MBM, 3), 256, GSMEM_BYTES>>>(
        p_x2, p_wqr, p_wkr, p_wvr, bq, bk, bv, nullptr, p_q, p_k, p_v, DD, DD, 0);

    // 3) attention (tensor-core)
    attn_mma<<<dim3(SS / 64, BB * HH), 256, ATTN_SMEM_BYTES>>>(p_q, p_k, p_v, p_attn);

    // 4) residual + norm2 + threshold mask
    ln_kernel<<<NN, 256>>>(x, p_attn, p_xres, p_x2b, alpha2, bias2, 1);

    // 5) ffn1 + relu
    mma_gemm<<<dim3(FF / MBN, NN / MBM, 1), 256, GSMEM_BYTES>>>(
        p_x2b, p_w1r, p_w1r, p_w1r, b1, b1, b1, nullptr, p_h, p_h, p_h, DD, FF, 1);

    // 6) ffn2 + bias + residual -> out
    mma_gemm<<<dim3(DD / MBN, NN / MBM, 1), 256, GSMEM_BYTES>>>(
        p_h, p_w2r, p_w2r, p_w2r, b2, b2, b2, p_xres, out, out, out, FF, DD, 2);
}

// round 6
// speedup vs baseline: 3.6679x; 1.0655x over previous
#include <cuda_runtime.h>
#include <cuda_bf16.h>
#include <math.h>
#include <cstdint>

// ---------------------------------------------------------------------------
// Problem constants
// ---------------------------------------------------------------------------
#define BB 4
#define SS 2048
#define DD 1024
#define HH 16
#define DH 64
#define FF 4096
#define NN (BB * SS)
#define EPS 1e-6f
#define THRESH 0.15f
#define SCALE 0.125f

// ---------------------------------------------------------------------------
// Scratch
// ---------------------------------------------------------------------------
__device__ float g_x2  [NN * DD];
__device__ float g_q   [NN * DD];
__device__ float g_k   [NN * DD];
__device__ float g_v   [NN * DD];
__device__ float g_attn[NN * DD];
__device__ float g_xres[NN * DD];
__device__ float g_x2b [NN * DD];
__device__ float g_h   [NN * FF];
__device__ float g_wqr [DD * DD];
__device__ float g_wkr [DD * DD];
__device__ float g_wvr [DD * DD];
__device__ float g_w1r [FF * DD];
__device__ float g_w2r [DD * FF];

// ---------------------------------------------------------------------------
// helpers
// ---------------------------------------------------------------------------
__device__ __forceinline__ uint32_t smem_u32(const void* p) {
    uint32_t a;
    asm("{ .reg .u64 t; cvta.to.shared.u64 t, %1; cvt.u32.u64 %0, t; }"
        : "=r"(a) : "l"(p));
    return a;
}

__device__ __forceinline__ float rna_tf32(float x) {
    uint32_t r;
    asm("cvt.rna.tf32.f32 %0, %1;" : "=r"(r) : "f"(x));
    return __uint_as_float(r);
}

__device__ __forceinline__ void cp16(uint32_t dst, const void* src) {
    asm volatile("cp.async.cg.shared.global [%0], [%1], 16;" :: "r"(dst), "l"(src));
}
#define CP_COMMIT() asm volatile("cp.async.commit_group;" ::: "memory")
#define CP_WAIT0()  asm volatile("cp.async.wait_group 0;" ::: "memory")
#define CP_WAIT1()  asm volatile("cp.async.wait_group 1;" ::: "memory")

__device__ __forceinline__ void mma_tf32(float c[4], const uint32_t a[4],
                                         uint32_t b0, uint32_t b1) {
    asm volatile(
        "mma.sync.aligned.m16n8k8.row.col.f32.tf32.tf32.f32 "
        "{%0,%1,%2,%3}, {%4,%5,%6,%7}, {%8,%9}, {%0,%1,%2,%3};"
        : "+f"(c[0]), "+f"(c[1]), "+f"(c[2]), "+f"(c[3])
        : "r"(a[0]), "r"(a[1]), "r"(a[2]), "r"(a[3]), "r"(b0), "r"(b1));
}

// ---------------------------------------------------------------------------
// tf32 round pass for weights
// ---------------------------------------------------------------------------
__global__ __launch_bounds__(256) void round_tf32_kernel(
    const float* __restrict__ src, float* __restrict__ dst, int n4)
{
    int i = blockIdx.x * 256 + threadIdx.x;
    if (i < n4) {
        float4 v = ((const float4*)src)[i];
        v.x = rna_tf32(v.x); v.y = rna_tf32(v.y);
        v.z = rna_tf32(v.z); v.w = rna_tf32(v.w);
        ((float4*)dst)[i] = v;
    }
}

// ---------------------------------------------------------------------------
// tf32 mma.sync GEMM: C[M,O] = A[M,K] @ W[O,K]^T + bias  (+relu/+resid)
// 128x256 CTA tile, 64x64 warp tile (8 warps 2x4), BK=32, 3-stage cp.async.
// mode: 0 = plain + tf32-round, 1 = relu + tf32-round, 2 = add resid
// ---------------------------------------------------------------------------
#define MBK  32
#define MBM  128
#define MBN  256
#define APAD 36
#define ASTG (MBM * APAD)                   // 4608 floats / stage
#define BSTG (MBN * APAD)                   // 9216 floats / stage
#define NSTAGE 3
#define GSMEM_BYTES ((ASTG + BSTG) * NSTAGE * 4)   // 165888 B

__global__ __launch_bounds__(256, 1) void mma_gemm(
    const float* __restrict__ A,
    const float* __restrict__ W0, const float* __restrict__ W1, const float* __restrict__ W2,
    const float* __restrict__ bi0, const float* __restrict__ bi1, const float* __restrict__ bi2,
    const float* __restrict__ resid,
    float* __restrict__ C0, float* __restrict__ C1, float* __restrict__ C2,
    int K, int ldc, int mode)
{
    extern __shared__ __align__(16) float sm[];
    float* As = sm;                          // [NSTAGE][ASTG]
    float* Bs = sm + NSTAGE * ASTG;          // [NSTAGE][BSTG]
    const uint32_t sA = smem_u32(As);
    const uint32_t sB = smem_u32(Bs);

    const float* W    = (blockIdx.z == 0) ? W0  : (blockIdx.z == 1) ? W1  : W2;
    const float* bias = (blockIdx.z == 0) ? bi0 : (blockIdx.z == 1) ? bi1 : bi2;
    float*       C    = (blockIdx.z == 0) ? C0  : (blockIdx.z == 1) ? C1  : C2;

    const int tid    = threadIdx.x;
    const int wid    = tid >> 5;
    const int lane   = tid & 31;
    const int warp_m = wid >> 2;             // 0..1
    const int warp_n = wid & 3;              // 0..3
    const int g      = lane >> 2;            // 0..7
    const int t4     = lane & 3;             // 0..3

    const int row0 = blockIdx.y * MBM;
    const int col0 = blockIdx.x * MBN;

    const float* gA = A + (size_t)row0 * K;
    const float* gW = W + (size_t)col0 * K;

    const int lrow = tid >> 3;               // 0..31
    const int lkc  = (tid & 7) * 4;          // float offset within BK

    float acc[4][8][4];
    #pragma unroll
    for (int mt = 0; mt < 4; mt++)
        #pragma unroll
        for (int nt = 0; nt < 8; nt++)
            #pragma unroll
            for (int j = 0; j < 4; j++) acc[mt][nt][j] = 0.0f;

    const int NT = K / MBK;

    auto load_stage = [&](int buf, int kt) {
        const size_t kof = (size_t)kt * MBK + lkc;
        const uint32_t da = sA + (buf * ASTG) * 4;
        const uint32_t db = sB + (buf * BSTG) * 4;
        #pragma unroll
        for (int i = 0; i < 4; i++) {
            const int r = lrow + 32 * i;
            cp16(da + (r * APAD + lkc) * 4, gA + (size_t)r * K + kof);
        }
        #pragma unroll
        for (int i = 0; i < 8; i++) {
            const int r = lrow + 32 * i;
            cp16(db + (r * APAD + lkc) * 4, gW + (size_t)r * K + kof);
        }
    };

    load_stage(0, 0);
    CP_COMMIT();
    load_stage(1, 1);
    CP_COMMIT();

    const uint32_t* Asu = (const uint32_t*)As;
    const uint32_t* Bsu = (const uint32_t*)Bs;

    int buf = 0;
    for (int t = 0; t < NT; t++) {
        CP_WAIT1();
        __syncthreads();

        const uint32_t* sa = Asu + buf * ASTG + (warp_m * 64 + g) * APAD + t4;
        const uint32_t* sb = Bsu + buf * BSTG + (warp_n * 64 + g) * APAD + t4;

        #pragma unroll
        for (int ks = 0; ks < 4; ks++) {
            const int k = ks * 8;
            uint32_t a[4][4];
            #pragma unroll
            for (int mt = 0; mt < 4; mt++) {
                const uint32_t* ap = sa + (mt * 16) * APAD + k;
                a[mt][0] = ap[0];
                a[mt][1] = ap[8 * APAD];
                a[mt][2] = ap[4];
                a[mt][3] = ap[8 * APAD + 4];
            }
            #pragma unroll
            for (int nt = 0; nt < 8; nt++) {
                const uint32_t* bp = sb + (nt * 8) * APAD + k;
                const uint32_t b0 = bp[0];
                const uint32_t b1 = bp[4];
                #pragma unroll
                for (int mt = 0; mt < 4; mt++)
                    mma_tf32(acc[mt][nt], a[mt], b0, b1);
            }
        }

        if (t + 2 < NT) {
            load_stage((buf + 2 >= NSTAGE) ? buf + 2 - NSTAGE : buf + 2, t + 2);
            CP_COMMIT();
        }
        buf = (buf + 1 == NSTAGE) ? 0 : buf + 1;
    }

    // epilogue
    const int rb = row0 + warp_m * 64 + g;
    const int cb = col0 + warp_n * 64 + t4 * 2;
    #pragma unroll
    for (int mt = 0; mt < 4; mt++) {
        const int r = rb + mt * 16;
        #pragma unroll
        for (int nt = 0; nt < 8; nt++) {
            const int c = cb + nt * 8;
            const float2 bv = *(const float2*)(bias + c);
            float2 v0, v1;
            v0.x = acc[mt][nt][0] + bv.x;
            v0.y = acc[mt][nt][1] + bv.y;
            v1.x = acc[mt][nt][2] + bv.x;
            v1.y = acc[mt][nt][3] + bv.y;
            if (mode == 0) {
                v0.x = rna_tf32(v0.x); v0.y = rna_tf32(v0.y);
                v1.x = rna_tf32(v1.x); v1.y = rna_tf32(v1.y);
            } else if (mode == 1) {
                v0.x = rna_tf32(fmaxf(v0.x, 0.0f));
                v0.y = rna_tf32(fmaxf(v0.y, 0.0f));
                v1.x = rna_tf32(fmaxf(v1.x, 0.0f));
                v1.y = rna_tf32(fmaxf(v1.y, 0.0f));
            } else if (mode == 2) {
                const float2 r0 = *(const float2*)(resid + (size_t)r * ldc + c);
                const float2 r1 = *(const float2*)(resid + (size_t)(r + 8) * ldc + c);
                v0.x += r0.x; v0.y += r0.y;
                v1.x += r1.x; v1.y += r1.y;
            }
            *(float2*)(C + (size_t)r * ldc + c)       = v0;
            *(float2*)(C + (size_t)(r + 8) * ldc + c) = v1;
        }
    }
}

// ---------------------------------------------------------------------------
// LayerNorm — output tf32-rounded
// ---------------------------------------------------------------------------
__global__ __launch_bounds__(256) void ln_kernel(
    const float* __restrict__ x,
    const float* __restrict__ resid,
    float*       __restrict__ out_res,
    float*       __restrict__ out_norm,
    const float* __restrict__ alpha,
    const float* __restrict__ beta,
    int apply_mask)
{
    __shared__ float red[256];
    const int n   = blockIdx.x;
    const int tid = threadIdx.x;
    const size_t off = (size_t)n * DD;
    const int d4 = tid * 4;

    float4 xv = *(const float4*)(x + off + d4);
    if (resid) {
        float4 rv = *(const float4*)(resid + off + d4);
        xv.x += rv.x; xv.y += rv.y; xv.z += rv.z; xv.w += rv.w;
    }
    if (out_res) *(float4*)(out_res + off + d4) = xv;

    float s = xv.x + xv.y + xv.z + xv.w;
    red[tid] = s;
    __syncthreads();
    #pragma unroll
    for (int st = 128; st > 0; st >>= 1) {
        if (tid < st) red[tid] += red[tid + st];
        __syncthreads();
    }
    const float mu = red[0] * (1.0f / DD);
    __syncthreads();

    float dx0 = xv.x - mu, dx1 = xv.y - mu, dx2 = xv.z - mu, dx3 = xv.w - mu;
    red[tid] = dx0*dx0 + dx1*dx1 + dx2*dx2 + dx3*dx3;
    __syncthreads();
    #pragma unroll
    for (int st = 128; st > 0; st >>= 1) {
        if (tid < st) red[tid] += red[tid + st];
        __syncthreads();
    }
    const float var = red[0] * (1.0f / (DD - 1));
    const float inv = 1.0f / (sqrtf(var) + EPS);

    float4 av = *(const float4*)(alpha + d4);
    float4 bv = *(const float4*)(beta  + d4);
    float4 y;
    y.x = av.x * dx0 * inv + bv.x;
    y.y = av.y * dx1 * inv + bv.y;
    y.z = av.z * dx2 * inv + bv.z;
    y.w = av.w * dx3 * inv + bv.w;
    if (apply_mask) {
        if (y.x < THRESH) y.x = 0.0f;
        if (y.y < THRESH) y.y = 0.0f;
        if (y.z < THRESH) y.z = 0.0f;
        if (y.w < THRESH) y.w = 0.0f;
    }
    y.x = rna_tf32(y.x); y.y = rna_tf32(y.y);
    y.z = rna_tf32(y.z); y.w = rna_tf32(y.w);
    *(float4*)(out_norm + off + d4) = y;
}

// ---------------------------------------------------------------------------
// Tensor-core flash attention (tf32 mma.sync) — unchanged from R5
// ---------------------------------------------------------------------------
#define AST 68
#define VST 72
#define ATTN_SMEM_FLOATS (3 * 64 * AST + 64 * VST + 3 * 64)
#define ATTN_SMEM_BYTES  (ATTN_SMEM_FLOATS * 4)

__global__ __launch_bounds__(256, 2) void attn_mma(
    const float* __restrict__ Q,
    const float* __restrict__ Km,
    const float* __restrict__ Vm,
    float*       __restrict__ O)
{
    extern __shared__ __align__(16) float fsm[];
    float* Qs   = fsm;
    float* Ks   = Qs + 64 * AST;
    float* Vs   = Ks + 64 * AST;
    float* Ss   = Vs + 64 * VST;
    float* mrow = Ss + 64 * AST;
    float* lrow = mrow + 64;
    float* crow = lrow + 64;
    const uint32_t sKu = smem_u32(Ks);
    const uint32_t sVu = smem_u32(Vs);

    const int qb  = blockIdx.x;
    const int bh  = blockIdx.y;
    const int b   = bh >> 4;
    const int h   = bh & 15;
    const int tid = threadIdx.x;
    const int wid    = tid >> 5;
    const int lane   = tid & 31;
    const int warp_m = wid >> 1;
    const int warp_n = wid & 1;
    const int g      = lane >> 2;
    const int t4     = lane & 3;

    const size_t base = (size_t)b * SS * DD + (size_t)h * DH;
    const int q0 = qb * 64;

    for (int t = tid; t < 64 * 16; t += 256) {
        const int r  = t >> 4;
        const int d4 = (t & 15) << 2;
        *(float4*)&Qs[r * AST + d4] =
            *(const float4*)(Q + base + (size_t)(q0 + r) * DD + d4);
    }
    if (tid < 64) { mrow[tid] = -1e30f; lrow[tid] = 0.0f; }

    float acc_o[4][4];
    #pragma unroll
    for (int nt = 0; nt < 4; nt++)
        #pragma unroll
        for (int j = 0; j < 4; j++) acc_o[nt][j] = 0.0f;

    const int lr = tid >> 4;
    const int lc = (tid & 15) << 2;

    __syncthreads();

    const uint32_t* Qsu = (const uint32_t*)Qs;
    const uint32_t* Ksu = (const uint32_t*)Ks;
    const uint32_t* Vsu = (const uint32_t*)Vs;
    const uint32_t* Ssu = (const uint32_t*)Ss;

    for (int kt = 0; kt < SS / 64; kt++) {
        const int k0 = kt * 64;

        #pragma unroll
        for (int i = 0; i < 4; i++) {
            const int r = lr + 16 * i;
            const float* kg = Km + base + (size_t)(k0 + r) * DD + lc;
            const float* vg = Vm + base + (size_t)(k0 + r) * DD + lc;
            cp16(sKu + (r * AST + lc) * 4, kg);
            cp16(sVu + (r * VST + lc) * 4, vg);
        }
        CP_COMMIT();
        CP_WAIT0();
        __syncthreads();

        float accs[4][4];
        #pragma unroll
        for (int nt = 0; nt < 4; nt++)
            #pragma unroll
            for (int j = 0; j < 4; j++) accs[nt][j] = 0.0f;

        const uint32_t* sa = Qsu + (warp_m * 16 + g) * AST + t4;
        const uint32_t* sb = Ksu + (warp_n * 32 + g) * AST + t4;
        #pragma unroll
        for (int ks = 0; ks < 8; ks++) {
            const int k = ks * 8;
            uint32_t a[4];
            a[0] = sa[k];
            a[1] = sa[8 * AST + k];
            a[2] = sa[k + 4];
            a[3] = sa[8 * AST + k + 4];
            #pragma unroll
            for (int nt = 0; nt < 4; nt++) {
                const uint32_t* bp = sb + (nt * 8) * AST + k;
                mma_tf32(accs[nt], a, bp[0], bp[4]);
            }
        }

        {
            const int r0 = warp_m * 16 + g;
            const int c0 = warp_n * 32 + 2 * t4;
            #pragma unroll
            for (int nt = 0; nt < 4; nt++) {
                const int c = c0 + nt * 8;
                float2 lo, hi;
                lo.x = accs[nt][0] * SCALE; lo.y = accs[nt][1] * SCALE;
                hi.x = accs[nt][2] * SCALE; hi.y = accs[nt][3] * SCALE;
                *(float2*)&Ss[r0 * AST + c]       = lo;
                *(float2*)&Ss[(r0 + 8) * AST + c] = hi;
            }
        }
        __syncthreads();

        {
            const int r   = tid >> 2;
            const int sub = tid & 3;
            float* srow = &Ss[r * AST + sub * 16];
            float mt = -1e30f;
            #pragma unroll
            for (int c = 0; c < 16; c++) mt = fmaxf(mt, srow[c]);
            mt = fmaxf(mt, __shfl_xor_sync(0xffffffff, mt, 1));
            mt = fmaxf(mt, __shfl_xor_sync(0xffffffff, mt, 2));
            const float mold = mrow[r];
            const float mnew = fmaxf(mold, mt);
            float ls = 0.0f;
            #pragma unroll
            for (int c = 0; c < 16; c++) {
                float p = rna_tf32(__expf(srow[c] - mnew));
                srow[c] = p;
                ls += p;
            }
            ls += __shfl_xor_sync(0xffffffff, ls, 1);
            ls += __shfl_xor_sync(0xffffffff, ls, 2);
            if (sub == 0) {
                const float corr = __expf(mold - mnew);
                crow[r] = corr;
                lrow[r] = lrow[r] * corr + ls;
                mrow[r] = mnew;
            }
        }
        __syncthreads();

        {
            const float cf0 = crow[warp_m * 16 + g];
            const float cf1 = crow[warp_m * 16 + g + 8];
            #pragma unroll
            for (int nt = 0; nt < 4; nt++) {
                acc_o[nt][0] *= cf0; acc_o[nt][1] *= cf0;
                acc_o[nt][2] *= cf1; acc_o[nt][3] *= cf1;
            }
        }

        {
            const uint32_t* pa = Ssu + (warp_m * 16 + g) * AST + t4;
            const uint32_t* pb = Vsu + t4 * VST + warp_n * 32 + g;
            #pragma unroll
            for (int ks = 0; ks < 8; ks++) {
                const int k = ks * 8;
                uint32_t a[4];
                a[0] = pa[k];
                a[1] = pa[8 * AST + k];
                a[2] = pa[k + 4];
                a[3] = pa[8 * AST + k + 4];
                const uint32_t* bp = pb + ks * 8 * VST;
                #pragma unroll
                for (int nt = 0; nt < 4; nt++) {
                    mma_tf32(acc_o[nt], a, bp[nt * 8], bp[4 * VST + nt * 8]);
                }
            }
        }
        __syncthreads();
    }

    {
        const int r0 = warp_m * 16 + g;
        const float li0 = 1.0f / lrow[r0];
        const float li1 = 1.0f / lrow[r0 + 8];
        const size_t ro0 = base + (size_t)(q0 + r0) * DD;
        const size_t ro1 = base + (size_t)(q0 + r0 + 8) * DD;
        const int c0 = warp_n * 32 + 2 * t4;
        #pragma unroll
        for (int nt = 0; nt < 4; nt++) {
            const int c = c0 + nt * 8;
            float2 lo, hi;
            lo.x = acc_o[nt][0] * li0; lo.y = acc_o[nt][1] * li0;
            hi.x = acc_o[nt][2] * li1; hi.y = acc_o[nt][3] * li1;
            *(float2*)(O + ro0 + c) = lo;
            *(float2*)(O + ro1 + c) = hi;
        }
    }
}

// ---------------------------------------------------------------------------
// launch
// ---------------------------------------------------------------------------
extern "C" void kernel_launch(void* const* d_in, const int* in_sizes, int n_in,
                              void* d_out, int out_size)
{
    const float* x      = (const float*)d_in[0];
    const float* alpha1 = (const float*)d_in[1];
    const float* bias1  = (const float*)d_in[2];
    const float* alpha2 = (const float*)d_in[3];
    const float* bias2  = (const float*)d_in[4];
    const float* wq     = (const float*)d_in[5];
    const float* bq     = (const float*)d_in[6];
    const float* wk     = (const float*)d_in[7];
    const float* bk     = (const float*)d_in[8];
    const float* wv     = (const float*)d_in[9];
    const float* bv     = (const float*)d_in[10];
    const float* w1     = (const float*)d_in[11];
    const float* b1     = (const float*)d_in[12];
    const float* w2     = (const float*)d_in[13];
    const float* b2     = (const float*)d_in[14];
    float* out = (float*)d_out;

    float *p_x2, *p_q, *p_k, *p_v, *p_attn, *p_xres, *p_x2b, *p_h;
    float *p_wqr, *p_wkr, *p_wvr, *p_w1r, *p_w2r;
    cudaGetSymbolAddress((void**)&p_x2,   g_x2);
    cudaGetSymbolAddress((void**)&p_q,    g_q);
    cudaGetSymbolAddress((void**)&p_k,    g_k);
    cudaGetSymbolAddress((void**)&p_v,    g_v);
    cudaGetSymbolAddress((void**)&p_attn, g_attn);
    cudaGetSymbolAddress((void**)&p_xres, g_xres);
    cudaGetSymbolAddress((void**)&p_x2b,  g_x2b);
    cudaGetSymbolAddress((void**)&p_h,    g_h);
    cudaGetSymbolAddress((void**)&p_wqr,  g_wqr);
    cudaGetSymbolAddress((void**)&p_wkr,  g_wkr);
    cudaGetSymbolAddress((void**)&p_wvr,  g_wvr);
    cudaGetSymbolAddress((void**)&p_w1r,  g_w1r);
    cudaGetSymbolAddress((void**)&p_w2r,  g_w2r);

    cudaFuncSetAttribute(attn_mma,
                         cudaFuncAttributeMaxDynamicSharedMemorySize, ATTN_SMEM_BYTES);
    cudaFuncSetAttribute(mma_gemm,
                         cudaFuncAttributeMaxDynamicSharedMemorySize, GSMEM_BYTES);

    // 0) tf32-round weights
    const int nqkv4 = DD * DD / 4, nff4 = FF * DD / 4;
    round_tf32_kernel<<<(nqkv4 + 255) / 256, 256>>>(wq, p_wqr, nqkv4);
    round_tf32_kernel<<<(nqkv4 + 255) / 256, 256>>>(wk, p_wkr, nqkv4);
    round_tf32_kernel<<<(nqkv4 + 255) / 256, 256>>>(wv, p_wvr, nqkv4);
    round_tf32_kernel<<<(nff4  + 255) / 256, 256>>>(w1, p_w1r, nff4);
    round_tf32_kernel<<<(nff4  + 255) / 256, 256>>>(w2, p_w2r, nff4);

    // 1) norm1
    ln_kernel<<<NN, 256>>>(x, nullptr, nullptr, p_x2, alpha1, bias1, 0);

    // 2) fused q,k,v projections
    mma_gemm<<<dim3(DD / MBN, NN / MBM, 3), 256, GSMEM_BYTES>>>(
        p_x2, p_wqr, p_wkr, p_wvr, bq, bk, bv, nullptr, p_q, p_k, p_v, DD, DD, 0);

    // 3) attention
    attn_mma<<<dim3(SS / 64, BB * HH), 256, ATTN_SMEM_BYTES>>>(p_q, p_k, p_v, p_attn);

    // 4) residual + norm2 + threshold mask
    ln_kernel<<<NN, 256>>>(x, p_attn, p_xres, p_x2b, alpha2, bias2, 1);

    // 5) ffn1 + relu
    mma_gemm<<<dim3(FF / MBN, NN / MBM, 1), 256, GSMEM_BYTES>>>(
        p_x2b, p_w1r, p_w1r, p_w1r, b1, b1, b1, nullptr, p_h, p_h, p_h, DD, FF, 1);

    // 6) ffn2 + bias + residual -> out
    mma_gemm<<<dim3(DD / MBN, NN / MBM, 1), 256, GSMEM_BYTES>>>(
        p_h, p_w2r, p_w2r, p_w2r, b2, b2, b2, p_xres, out, out, out, FF, DD, 2);
}

// round 7
// speedup vs baseline: 5.3470x; 1.4578x over previous
#include <cuda_runtime.h>
#include <cuda_fp16.h>
#include <math.h>
#include <cstdint>

// ---------------------------------------------------------------------------
// Problem constants
// ---------------------------------------------------------------------------
#define BB 4
#define SS 2048
#define DD 1024
#define HH 16
#define DH 64
#define FF 4096
#define NN (BB * SS)
#define EPS 1e-6f
#define THRESH 0.15f
#define SCALE 0.125f

// ---------------------------------------------------------------------------
// Scratch (half activations, half weights; fp32 residual path)
// ---------------------------------------------------------------------------
__device__ __half g_x2  [NN * DD];
__device__ __half g_q   [NN * DD];
__device__ __half g_k   [NN * DD];
__device__ __half g_v   [NN * DD];
__device__ float  g_attn[NN * DD];
__device__ float  g_xres[NN * DD];
__device__ __half g_x2b [NN * DD];
__device__ __half g_h   [NN * FF];
__device__ __half g_wqh [DD * DD];
__device__ __half g_wkh [DD * DD];
__device__ __half g_wvh [DD * DD];
__device__ __half g_w1h [FF * DD];
__device__ __half g_w2h [DD * FF];

// ---------------------------------------------------------------------------
// helpers
// ---------------------------------------------------------------------------
__device__ __forceinline__ uint32_t smem_u32(const void* p) {
    uint32_t a;
    asm("{ .reg .u64 t; cvta.to.shared.u64 t, %1; cvt.u32.u64 %0, t; }"
        : "=r"(a) : "l"(p));
    return a;
}

__device__ __forceinline__ void cp16(uint32_t dst, const void* src) {
    asm volatile("cp.async.cg.shared.global [%0], [%1], 16;" :: "r"(dst), "l"(src));
}
#define CP_COMMIT() asm volatile("cp.async.commit_group;" ::: "memory")
#define CP_WAIT0()  asm volatile("cp.async.wait_group 0;" ::: "memory")
#define CP_WAIT1()  asm volatile("cp.async.wait_group 1;" ::: "memory")

__device__ __forceinline__ void mma_f16(float c[4], const uint32_t a[4],
                                        uint32_t b0, uint32_t b1) {
    asm volatile(
        "mma.sync.aligned.m16n8k16.row.col.f32.f16.f16.f32 "
        "{%0,%1,%2,%3}, {%4,%5,%6,%7}, {%8,%9}, {%0,%1,%2,%3};"
        : "+f"(c[0]), "+f"(c[1]), "+f"(c[2]), "+f"(c[3])
        : "r"(a[0]), "r"(a[1]), "r"(a[2]), "r"(a[3]), "r"(b0), "r"(b1));
}

#define LDMX4(r, addr)                                                        \
    asm volatile("ldmatrix.sync.aligned.m8n8.x4.shared.b16 {%0,%1,%2,%3}, [%4];" \
        : "=r"((r)[0]), "=r"((r)[1]), "=r"((r)[2]), "=r"((r)[3]) : "r"(addr))
#define LDMX4T(r, addr)                                                       \
    asm volatile("ldmatrix.sync.aligned.m8n8.x4.trans.shared.b16 {%0,%1,%2,%3}, [%4];" \
        : "=r"((r)[0]), "=r"((r)[1]), "=r"((r)[2]), "=r"((r)[3]) : "r"(addr))

// ---------------------------------------------------------------------------
// float -> half conversion (weights)
// ---------------------------------------------------------------------------
__global__ __launch_bounds__(256) void cvt_f2h_kernel(
    const float* __restrict__ src, __half* __restrict__ dst, int n4)
{
    int i = blockIdx.x * 256 + threadIdx.x;
    if (i < n4) {
        float4 v = ((const float4*)src)[i];
        __half2 h0 = __floats2half2_rn(v.x, v.y);
        __half2 h1 = __floats2half2_rn(v.z, v.w);
        uint2 pk;
        pk.x = *(uint32_t*)&h0;
        pk.y = *(uint32_t*)&h1;
        ((uint2*)dst)[i] = pk;
    }
}

// ---------------------------------------------------------------------------
// fp16 mma.sync GEMM: C[M,O] = A[M,K] @ W[O,K]^T + bias  (+relu/+resid)
// 128x256 CTA, 64x64 warp tile (8 warps 2x4), BK=64 halves, 3-stage cp.async.
// ldmatrix.x4 fragment loads. mode: 0 = half out, 1 = relu half out,
// 2 = float out + resid.
// ---------------------------------------------------------------------------
#define MBK  64                               // halves per k-tile
#define MBM  128
#define MBN  256
#define APADH 36                              // half2 (u32) units per row
#define ASTG (MBM * APADH)                    // u32 per A stage
#define BSTG (MBN * APADH)                    // u32 per B stage
#define NSTAGE 3
#define GSMEM_BYTES ((ASTG + BSTG) * NSTAGE * 4)   // 165888 B

__global__ __launch_bounds__(256, 1) void mma_gemm(
    const __half* __restrict__ A,
    const __half* __restrict__ W0, const __half* __restrict__ W1, const __half* __restrict__ W2,
    const float* __restrict__ bi0, const float* __restrict__ bi1, const float* __restrict__ bi2,
    const float* __restrict__ resid,
    __half* __restrict__ H0, __half* __restrict__ H1, __half* __restrict__ H2,
    float* __restrict__ Cf,
    int K, int ldc, int mode)
{
    extern __shared__ __align__(16) uint32_t smu[];
    const uint32_t sAb = smem_u32(smu);                    // byte addr of A stages
    const uint32_t sBb = sAb + NSTAGE * ASTG * 4;

    const __half* W    = (blockIdx.z == 0) ? W0  : (blockIdx.z == 1) ? W1  : W2;
    const float*  bias = (blockIdx.z == 0) ? bi0 : (blockIdx.z == 1) ? bi1 : bi2;
    __half*       Ch   = (blockIdx.z == 0) ? H0  : (blockIdx.z == 1) ? H1  : H2;

    const int tid    = threadIdx.x;
    const int wid    = tid >> 5;
    const int lane   = tid & 31;
    const int warp_m = wid >> 2;              // 0..1
    const int warp_n = wid & 3;               // 0..3
    const int g      = lane >> 2;
    const int t4     = lane & 3;

    const int row0 = blockIdx.y * MBM;
    const int col0 = blockIdx.x * MBN;

    const __half* gA = A + (size_t)row0 * K;
    const __half* gW = W + (size_t)col0 * K;

    const int lrow = tid >> 3;                // 0..31
    const int lch  = tid & 7;                 // chunk within row

    // per-lane ldmatrix base offsets (u32 units)
    const uint32_t a_lane = (uint32_t)((warp_m * 64 + (lane & 15)) * APADH + ((lane >> 4) << 2));
    const uint32_t b_lane = (uint32_t)((warp_n * 64 + (lane & 7) + ((lane >> 4) << 3)) * APADH
                                       + (((lane >> 3) & 1) << 2));

    float acc[4][8][4];
    #pragma unroll
    for (int mt = 0; mt < 4; mt++)
        #pragma unroll
        for (int nt = 0; nt < 8; nt++)
            #pragma unroll
            for (int j = 0; j < 4; j++) acc[mt][nt][j] = 0.0f;

    const int NT = K / MBK;

    auto load_stage = [&](int buf, int kt) {
        const size_t kof = (size_t)kt * MBK + lch * 8;     // halves
        const uint32_t da = sAb + (buf * ASTG) * 4;
        const uint32_t db = sBb + (buf * BSTG) * 4;
        #pragma unroll
        for (int i = 0; i < 4; i++) {
            const int r = lrow + 32 * i;
            cp16(da + (r * APADH + lch * 4) * 4, gA + (size_t)r * K + kof);
        }
        #pragma unroll
        for (int i = 0; i < 8; i++) {
            const int r = lrow + 32 * i;
            cp16(db + (r * APADH + lch * 4) * 4, gW + (size_t)r * K + kof);
        }
    };

    load_stage(0, 0);
    CP_COMMIT();
    load_stage(1, 1);
    CP_COMMIT();

    int buf = 0;
    for (int t = 0; t < NT; t++) {
        CP_WAIT1();
        __syncthreads();

        const uint32_t abase = sAb + (buf * ASTG + a_lane) * 4;
        const uint32_t bbase = sBb + (buf * BSTG + b_lane) * 4;

        #pragma unroll
        for (int ks = 0; ks < 4; ks++) {
            uint32_t a[4][4], bb[4][4];
            #pragma unroll
            for (int mt = 0; mt < 4; mt++)
                LDMX4(a[mt], abase + (mt * 16 * APADH + ks * 8) * 4);
            #pragma unroll
            for (int ntp = 0; ntp < 4; ntp++)
                LDMX4(bb[ntp], bbase + (ntp * 16 * APADH + ks * 8) * 4);
            #pragma unroll
            for (int mt = 0; mt < 4; mt++)
                #pragma unroll
                for (int ntp = 0; ntp < 4; ntp++) {
                    mma_f16(acc[mt][2 * ntp],     a[mt], bb[ntp][0], bb[ntp][1]);
                    mma_f16(acc[mt][2 * ntp + 1], a[mt], bb[ntp][2], bb[ntp][3]);
                }
        }

        if (t + 2 < NT) {
            load_stage((buf + 2 >= NSTAGE) ? buf + 2 - NSTAGE : buf + 2, t + 2);
            CP_COMMIT();
        }
        buf = (buf + 1 == NSTAGE) ? 0 : buf + 1;
    }

    // epilogue
    const int rb = row0 + warp_m * 64 + g;
    const int cb = col0 + warp_n * 64 + t4 * 2;
    #pragma unroll
    for (int mt = 0; mt < 4; mt++) {
        const int r = rb + mt * 16;
        #pragma unroll
        for (int nt = 0; nt < 8; nt++) {
            const int c = cb + nt * 8;
            const float2 bv = *(const float2*)(bias + c);
            float2 v0, v1;
            v0.x = acc[mt][nt][0] + bv.x;
            v0.y = acc[mt][nt][1] + bv.y;
            v1.x = acc[mt][nt][2] + bv.x;
            v1.y = acc[mt][nt][3] + bv.y;
            if (mode == 2) {
                const float2 r0 = *(const float2*)(resid + (size_t)r * ldc + c);
                const float2 r1 = *(const float2*)(resid + (size_t)(r + 8) * ldc + c);
                v0.x += r0.x; v0.y += r0.y;
                v1.x += r1.x; v1.y += r1.y;
                *(float2*)(Cf + (size_t)r * ldc + c)       = v0;
                *(float2*)(Cf + (size_t)(r + 8) * ldc + c) = v1;
            } else {
                if (mode == 1) {
                    v0.x = fmaxf(v0.x, 0.0f); v0.y = fmaxf(v0.y, 0.0f);
                    v1.x = fmaxf(v1.x, 0.0f); v1.y = fmaxf(v1.y, 0.0f);
                }
                __half2 h0 = __floats2half2_rn(v0.x, v0.y);
                __half2 h1 = __floats2half2_rn(v1.x, v1.y);
                *(uint32_t*)(Ch + (size_t)r * ldc + c)       = *(uint32_t*)&h0;
                *(uint32_t*)(Ch + (size_t)(r + 8) * ldc + c) = *(uint32_t*)&h1;
            }
        }
    }
}

// ---------------------------------------------------------------------------
// LayerNorm — half output (+ fp32 residual in/out, mask)
// ---------------------------------------------------------------------------
__global__ __launch_bounds__(256) void ln_kernel(
    const float* __restrict__ x,
    const float* __restrict__ resid,
    float*       __restrict__ out_res,
    __half*      __restrict__ out_norm,
    const float* __restrict__ alpha,
    const float* __restrict__ beta,
    int apply_mask)
{
    __shared__ float red[256];
    const int n   = blockIdx.x;
    const int tid = threadIdx.x;
    const size_t off = (size_t)n * DD;
    const int d4 = tid * 4;

    float4 xv = *(const float4*)(x + off + d4);
    if (resid) {
        float4 rv = *(const float4*)(resid + off + d4);
        xv.x += rv.x; xv.y += rv.y; xv.z += rv.z; xv.w += rv.w;
    }
    if (out_res) *(float4*)(out_res + off + d4) = xv;

    float s = xv.x + xv.y + xv.z + xv.w;
    red[tid] = s;
    __syncthreads();
    #pragma unroll
    for (int st = 128; st > 0; st >>= 1) {
        if (tid < st) red[tid] += red[tid + st];
        __syncthreads();
    }
    const float mu = red[0] * (1.0f / DD);
    __syncthreads();

    float dx0 = xv.x - mu, dx1 = xv.y - mu, dx2 = xv.z - mu, dx3 = xv.w - mu;
    red[tid] = dx0*dx0 + dx1*dx1 + dx2*dx2 + dx3*dx3;
    __syncthreads();
    #pragma unroll
    for (int st = 128; st > 0; st >>= 1) {
        if (tid < st) red[tid] += red[tid + st];
        __syncthreads();
    }
    const float var = red[0] * (1.0f / (DD - 1));
    const float inv = 1.0f / (sqrtf(var) + EPS);

    float4 av = *(const float4*)(alpha + d4);
    float4 bv = *(const float4*)(beta  + d4);
    float4 y;
    y.x = av.x * dx0 * inv + bv.x;
    y.y = av.y * dx1 * inv + bv.y;
    y.z = av.z * dx2 * inv + bv.z;
    y.w = av.w * dx3 * inv + bv.w;
    if (apply_mask) {
        if (y.x < THRESH) y.x = 0.0f;
        if (y.y < THRESH) y.y = 0.0f;
        if (y.z < THRESH) y.z = 0.0f;
        if (y.w < THRESH) y.w = 0.0f;
    }
    __half2 h0 = __floats2half2_rn(y.x, y.y);
    __half2 h1 = __floats2half2_rn(y.z, y.w);
    uint2 pk;
    pk.x = *(uint32_t*)&h0;
    pk.y = *(uint32_t*)&h1;
    *(uint2*)(out_norm + off + d4) = pk;
}

// ---------------------------------------------------------------------------
// fp16 tensor-core flash attention, ldmatrix fragments.
// 64 q-rows/block, 64-key tiles, 256 thr = 8 warps (4x2), warp tile 16x32.
// smem: Qs/Ks/Vs/Ps half [64][36 half2]; Ss float [64][68]; m/l/c rows.
// ---------------------------------------------------------------------------
#define HPAD 36                               // half2 units per 64-half row
#define HROW (64 * HPAD)                      // u32 per half tile
#define AST  68                               // float stride of Ss
#define SM_Q  0
#define SM_K  (HROW)
#define SM_V  (2 * HROW)
#define SM_P  (3 * HROW)
#define SM_S  (4 * HROW)                      // float region, u32 units
#define SM_M  (SM_S + 64 * AST)
#define SM_L  (SM_M + 64)
#define SM_C  (SM_L + 64)
#define ATTN_SMEM_BYTES ((SM_C + 64) * 4)     // 55,040 B

__global__ __launch_bounds__(256, 2) void attn_mma(
    const __half* __restrict__ Q,
    const __half* __restrict__ Km,
    const __half* __restrict__ Vm,
    float*        __restrict__ O)
{
    extern __shared__ __align__(16) uint32_t smu[];
    const uint32_t sb = smem_u32(smu);
    float* Ssf  = (float*)(smu + SM_S);
    float* mrow = (float*)(smu + SM_M);
    float* lrow = (float*)(smu + SM_L);
    float* crow = (float*)(smu + SM_C);
    __half* Ps  = (__half*)(smu + SM_P);

    const int qb  = blockIdx.x;
    const int bh  = blockIdx.y;
    const int b   = bh >> 4;
    const int h   = bh & 15;
    const int tid = threadIdx.x;
    const int lane   = tid & 31;
    const int wid    = tid >> 5;
    const int warp_m = wid >> 1;              // 0..3
    const int warp_n = wid & 1;               // 0..1
    const int g      = lane >> 2;
    const int t4     = lane & 3;

    const size_t base = (size_t)b * SS * DD + (size_t)h * DH;
    const int q0 = qb * 64;

    // ldmatrix lane bases (u32 units within a tile)
    const uint32_t qa_lane = (uint32_t)((warp_m * 16 + (lane & 15)) * HPAD + ((lane >> 4) << 2));
    const uint32_t kb_lane = (uint32_t)((warp_n * 32 + (lane & 7) + ((lane >> 4) << 3)) * HPAD
                                        + (((lane >> 3) & 1) << 2));
    const uint32_t vb_lane = (uint32_t)(((lane & 7) + (((lane >> 3) & 1) << 3)) * HPAD
                                        + warp_n * 16 + ((lane >> 4) << 2));

    // load Q tile (64 rows x 128 B)
    #pragma unroll
    for (int i = 0; i < 2; i++) {
        const int t = tid + 256 * i;
        const int r = t >> 3, c = t & 7;
        cp16(sb + (SM_Q + r * HPAD + c * 4) * 4, Q + base + (size_t)(q0 + r) * DD + c * 8);
    }
    CP_COMMIT();
    if (tid < 64) { mrow[tid] = -1e30f; lrow[tid] = 0.0f; }

    float acc_o[4][4];
    #pragma unroll
    for (int nt = 0; nt < 4; nt++)
        #pragma unroll
        for (int j = 0; j < 4; j++) acc_o[nt][j] = 0.0f;

    CP_WAIT0();
    __syncthreads();

    for (int kt = 0; kt < SS / 64; kt++) {
        const int k0 = kt * 64;

        // load K, V tiles
        #pragma unroll
        for (int i = 0; i < 2; i++) {
            const int t = tid + 256 * i;
            const int r = t >> 3, c = t & 7;
            cp16(sb + (SM_K + r * HPAD + c * 4) * 4, Km + base + (size_t)(k0 + r) * DD + c * 8);
            cp16(sb + (SM_V + r * HPAD + c * 4) * 4, Vm + base + (size_t)(k0 + r) * DD + c * 8);
        }
        CP_COMMIT();
        CP_WAIT0();
        __syncthreads();

        // --- S = Q K^T ---
        float accs[4][4];
        #pragma unroll
        for (int nt = 0; nt < 4; nt++)
            #pragma unroll
            for (int j = 0; j < 4; j++) accs[nt][j] = 0.0f;

        const uint32_t qb_ = sb + (SM_Q + qa_lane) * 4;
        const uint32_t kb_ = sb + (SM_K + kb_lane) * 4;
        #pragma unroll
        for (int ks = 0; ks < 4; ks++) {
            uint32_t a[4], bb0[4], bb1[4];
            LDMX4(a,   qb_ + (ks * 8) * 4);
            LDMX4(bb0, kb_ + (ks * 8) * 4);
            LDMX4(bb1, kb_ + (16 * HPAD + ks * 8) * 4);
            mma_f16(accs[0], a, bb0[0], bb0[1]);
            mma_f16(accs[1], a, bb0[2], bb0[3]);
            mma_f16(accs[2], a, bb1[0], bb1[1]);
            mma_f16(accs[3], a, bb1[2], bb1[3]);
        }

        // scaled scores -> Ss (float)
        {
            const int r0 = warp_m * 16 + g;
            const int c0 = warp_n * 32 + 2 * t4;
            #pragma unroll
            for (int nt = 0; nt < 4; nt++) {
                const int c = c0 + nt * 8;
                float2 lo, hi;
                lo.x = accs[nt][0] * SCALE; lo.y = accs[nt][1] * SCALE;
                hi.x = accs[nt][2] * SCALE; hi.y = accs[nt][3] * SCALE;
                *(float2*)&Ssf[r0 * AST + c]       = lo;
                *(float2*)&Ssf[(r0 + 8) * AST + c] = hi;
            }
        }
        __syncthreads();

        // --- online softmax; write probs to Ps (half) ---
        {
            const int r   = tid >> 2;
            const int sub = tid & 3;
            const float* srow = &Ssf[r * AST + sub * 16];
            __half* prow = &Ps[r * (HPAD * 2) + sub * 16];
            float mt = -1e30f;
            #pragma unroll
            for (int c = 0; c < 16; c++) mt = fmaxf(mt, srow[c]);
            mt = fmaxf(mt, __shfl_xor_sync(0xffffffff, mt, 1));
            mt = fmaxf(mt, __shfl_xor_sync(0xffffffff, mt, 2));
            const float mold = mrow[r];
            const float mnew = fmaxf(mold, mt);
            float ls = 0.0f;
            #pragma unroll
            for (int c = 0; c < 16; c++) {
                float p = __expf(srow[c] - mnew);
                prow[c] = __float2half_rn(p);
                ls += p;
            }
            ls += __shfl_xor_sync(0xffffffff, ls, 1);
            ls += __shfl_xor_sync(0xffffffff, ls, 2);
            if (sub == 0) {
                const float corr = __expf(mold - mnew);
                crow[r] = corr;
                lrow[r] = lrow[r] * corr + ls;
                mrow[r] = mnew;
            }
        }
        __syncthreads();

        // rescale accumulator
        {
            const float cf0 = crow[warp_m * 16 + g];
            const float cf1 = crow[warp_m * 16 + g + 8];
            #pragma unroll
            for (int nt = 0; nt < 4; nt++) {
                acc_o[nt][0] *= cf0; acc_o[nt][1] *= cf0;
                acc_o[nt][2] *= cf1; acc_o[nt][3] *= cf1;
            }
        }

        // --- acc_o += P V ---  (P: ldmatrix.x4, V: ldmatrix.x4.trans)
        {
            const uint32_t pb_ = sb + (SM_P + qa_lane) * 4;
            const uint32_t vb_ = sb + (SM_V + vb_lane) * 4;
            #pragma unroll
            for (int ks = 0; ks < 4; ks++) {
                uint32_t a[4], bb0[4], bb1[4];
                LDMX4(a, pb_ + (ks * 8) * 4);
                LDMX4T(bb0, vb_ + (ks * 16 * HPAD) * 4);
                LDMX4T(bb1, vb_ + (ks * 16 * HPAD + 8) * 4);
                mma_f16(acc_o[0], a, bb0[0], bb0[1]);
                mma_f16(acc_o[1], a, bb0[2], bb0[3]);
                mma_f16(acc_o[2], a, bb1[0], bb1[1]);
                mma_f16(acc_o[3], a, bb1[2], bb1[3]);
            }
        }
        __syncthreads();
    }

    // epilogue: divide by l, store fp32
    {
        const int r0 = warp_m * 16 + g;
        const float li0 = 1.0f / lrow[r0];
        const float li1 = 1.0f / lrow[r0 + 8];
        const size_t ro0 = base + (size_t)(q0 + r0) * DD;
        const size_t ro1 = base + (size_t)(q0 + r0 + 8) * DD;
        const int c0 = warp_n * 32 + 2 * t4;
        #pragma unroll
        for (int nt = 0; nt < 4; nt++) {
            const int c = c0 + nt * 8;
            float2 lo, hi;
            lo.x = acc_o[nt][0] * li0; lo.y = acc_o[nt][1] * li0;
            hi.x = acc_o[nt][2] * li1; hi.y = acc_o[nt][3] * li1;
            *(float2*)(O + ro0 + c) = lo;
            *(float2*)(O + ro1 + c) = hi;
        }
    }
}

// ---------------------------------------------------------------------------
// launch
// ---------------------------------------------------------------------------
extern "C" void kernel_launch(void* const* d_in, const int* in_sizes, int n_in,
                              void* d_out, int out_size)
{
    const float* x      = (const float*)d_in[0];
    const float* alpha1 = (const float*)d_in[1];
    const float* bias1  = (const float*)d_in[2];
    const float* alpha2 = (const float*)d_in[3];
    const float* bias2  = (const float*)d_in[4];
    const float* wq     = (const float*)d_in[5];
    const float* bq     = (const float*)d_in[6];
    const float* wk     = (const float*)d_in[7];
    const float* bk     = (const float*)d_in[8];
    const float* wv     = (const float*)d_in[9];
    const float* bv     = (const float*)d_in[10];
    const float* w1     = (const float*)d_in[11];
    const float* b1     = (const float*)d_in[12];
    const float* w2     = (const float*)d_in[13];
    const float* b2     = (const float*)d_in[14];
    float* out = (float*)d_out;

    __half *p_x2, *p_q, *p_k, *p_v, *p_x2b, *p_h;
    __half *p_wqh, *p_wkh, *p_wvh, *p_w1h, *p_w2h;
    float *p_attn, *p_xres;
    cudaGetSymbolAddress((void**)&p_x2,   g_x2);
    cudaGetSymbolAddress((void**)&p_q,    g_q);
    cudaGetSymbolAddress((void**)&p_k,    g_k);
    cudaGetSymbolAddress((void**)&p_v,    g_v);
    cudaGetSymbolAddress((void**)&p_attn, g_attn);
    cudaGetSymbolAddress((void**)&p_xres, g_xres);
    cudaGetSymbolAddress((void**)&p_x2b,  g_x2b);
    cudaGetSymbolAddress((void**)&p_h,    g_h);
    cudaGetSymbolAddress((void**)&p_wqh,  g_wqh);
    cudaGetSymbolAddress((void**)&p_wkh,  g_wkh);
    cudaGetSymbolAddress((void**)&p_wvh,  g_wvh);
    cudaGetSymbolAddress((void**)&p_w1h,  g_w1h);
    cudaGetSymbolAddress((void**)&p_w2h,  g_w2h);

    cudaFuncSetAttribute(attn_mma,
                         cudaFuncAttributeMaxDynamicSharedMemorySize, ATTN_SMEM_BYTES);
    cudaFuncSetAttribute(mma_gemm,
                         cudaFuncAttributeMaxDynamicSharedMemorySize, GSMEM_BYTES);

    // 0) convert weights to half
    const int nqkv4 = DD * DD / 4, nff4 = FF * DD / 4;
    cvt_f2h_kernel<<<(nqkv4 + 255) / 256, 256>>>(wq, p_wqh, nqkv4);
    cvt_f2h_kernel<<<(nqkv4 + 255) / 256, 256>>>(wk, p_wkh, nqkv4);
    cvt_f2h_kernel<<<(nqkv4 + 255) / 256, 256>>>(wv, p_wvh, nqkv4);
    cvt_f2h_kernel<<<(nff4  + 255) / 256, 256>>>(w1, p_w1h, nff4);
    cvt_f2h_kernel<<<(nff4  + 255) / 256, 256>>>(w2, p_w2h, nff4);

    // 1) norm1 (half out)
    ln_kernel<<<NN, 256>>>(x, nullptr, nullptr, p_x2, alpha1, bias1, 0);

    // 2) fused q,k,v projections (half out)
    mma_gemm<<<dim3(DD / MBN, NN / MBM, 3), 256, GSMEM_BYTES>>>(
        p_x2, p_wqh, p_wkh, p_wvh, bq, bk, bv, nullptr,
        p_q, p_k, p_v, nullptr, DD, DD, 0);

    // 3) attention (fp32 out)
    attn_mma<<<dim3(SS / 64, BB * HH), 256, ATTN_SMEM_BYTES>>>(p_q, p_k, p_v, p_attn);

    // 4) residual + norm2 + mask (half out, fp32 resid out)
    ln_kernel<<<NN, 256>>>(x, p_attn, p_xres, p_x2b, alpha2, bias2, 1);

    // 5) ffn1 + relu (half out)
    mma_gemm<<<dim3(FF / MBN, NN / MBM, 1), 256, GSMEM_BYTES>>>(
        p_x2b, p_w1h, p_w1h, p_w1h, b1, b1, b1, nullptr,
        p_h, p_h, p_h, nullptr, DD, FF, 1);

    // 6) ffn2 + bias + residual -> out (fp32)
    mma_gemm<<<dim3(DD / MBN, NN / MBM, 1), 256, GSMEM_BYTES>>>(
        p_h, p_w2h, p_w2h, p_w2h, b2, b2, b2, p_xres,
        nullptr, nullptr, nullptr, out, FF, DD, 2);
}

// round 8
// speedup vs baseline: 8.1423x; 1.5228x over previous
#include <cuda_runtime.h>
#include <cuda_fp16.h>
#include <math.h>
#include <cstdint>

// ---------------------------------------------------------------------------
// Problem constants
// ---------------------------------------------------------------------------
#define BB 4
#define SS 2048
#define DD 1024
#define HH 16
#define DH 64
#define FF 4096
#define NN (BB * SS)
#define EPS 1e-6f
#define THRESH 0.15f
#define SCALE 0.125f

// ---------------------------------------------------------------------------
// Scratch (half activations, half weights; fp32 residual path)
// ---------------------------------------------------------------------------
__device__ __half g_x2  [NN * DD];
__device__ __half g_q   [NN * DD];
__device__ __half g_k   [NN * DD];
__device__ __half g_v   [NN * DD];
__device__ float  g_attn[NN * DD];
__device__ float  g_xres[NN * DD];
__device__ __half g_x2b [NN * DD];
__device__ __half g_h   [NN * FF];
__device__ __half g_wqh [DD * DD];
__device__ __half g_wkh [DD * DD];
__device__ __half g_wvh [DD * DD];
__device__ __half g_w1h [FF * DD];
__device__ __half g_w2h [DD * FF];

// ---------------------------------------------------------------------------
// helpers
// ---------------------------------------------------------------------------
__device__ __forceinline__ uint32_t smem_u32(const void* p) {
    uint32_t a;
    asm("{ .reg .u64 t; cvta.to.shared.u64 t, %1; cvt.u32.u64 %0, t; }"
        : "=r"(a) : "l"(p));
    return a;
}

__device__ __forceinline__ void cp16(uint32_t dst, const void* src) {
    asm volatile("cp.async.cg.shared.global [%0], [%1], 16;" :: "r"(dst), "l"(src));
}
#define CP_COMMIT() asm volatile("cp.async.commit_group;" ::: "memory")
#define CP_WAIT1()  asm volatile("cp.async.wait_group 1;" ::: "memory")
#define CP_WAIT2()  asm volatile("cp.async.wait_group 2;" ::: "memory")

__device__ __forceinline__ void mma_f16(float c[4], const uint32_t a[4],
                                        uint32_t b0, uint32_t b1) {
    asm volatile(
        "mma.sync.aligned.m16n8k16.row.col.f32.f16.f16.f32 "
        "{%0,%1,%2,%3}, {%4,%5,%6,%7}, {%8,%9}, {%0,%1,%2,%3};"
        : "+f"(c[0]), "+f"(c[1]), "+f"(c[2]), "+f"(c[3])
        : "r"(a[0]), "r"(a[1]), "r"(a[2]), "r"(a[3]), "r"(b0), "r"(b1));
}

#define LDMX4(r, addr)                                                        \
    asm volatile("ldmatrix.sync.aligned.m8n8.x4.shared.b16 {%0,%1,%2,%3}, [%4];" \
        : "=r"((r)[0]), "=r"((r)[1]), "=r"((r)[2]), "=r"((r)[3]) : "r"(addr))
#define LDMX4T(r, addr)                                                       \
    asm volatile("ldmatrix.sync.aligned.m8n8.x4.trans.shared.b16 {%0,%1,%2,%3}, [%4];" \
        : "=r"((r)[0]), "=r"((r)[1]), "=r"((r)[2]), "=r"((r)[3]) : "r"(addr))

// ---------------------------------------------------------------------------
// float -> half conversion (weights)
// ---------------------------------------------------------------------------
__global__ __launch_bounds__(256) void cvt_f2h_kernel(
    const float* __restrict__ src, __half* __restrict__ dst, int n4)
{
    int i = blockIdx.x * 256 + threadIdx.x;
    if (i < n4) {
        float4 v = ((const float4*)src)[i];
        __half2 h0 = __floats2half2_rn(v.x, v.y);
        __half2 h1 = __floats2half2_rn(v.z, v.w);
        uint2 pk;
        pk.x = *(uint32_t*)&h0;
        pk.y = *(uint32_t*)&h1;
        ((uint2*)dst)[i] = pk;
    }
}

// ---------------------------------------------------------------------------
// fp16 mma.sync GEMM — unchanged from R7
// ---------------------------------------------------------------------------
#define MBK  64
#define MBM  128
#define MBN  256
#define APADH 36
#define ASTG (MBM * APADH)
#define BSTG (MBN * APADH)
#define NSTAGE 3
#define GSMEM_BYTES ((ASTG + BSTG) * NSTAGE * 4)

__global__ __launch_bounds__(256, 1) void mma_gemm(
    const __half* __restrict__ A,
    const __half* __restrict__ W0, const __half* __restrict__ W1, const __half* __restrict__ W2,
    const float* __restrict__ bi0, const float* __restrict__ bi1, const float* __restrict__ bi2,
    const float* __restrict__ resid,
    __half* __restrict__ H0, __half* __restrict__ H1, __half* __restrict__ H2,
    float* __restrict__ Cf,
    int K, int ldc, int mode)
{
    extern __shared__ __align__(16) uint32_t smu[];
    const uint32_t sAb = smem_u32(smu);
    const uint32_t sBb = sAb + NSTAGE * ASTG * 4;

    const __half* W    = (blockIdx.z == 0) ? W0  : (blockIdx.z == 1) ? W1  : W2;
    const float*  bias = (blockIdx.z == 0) ? bi0 : (blockIdx.z == 1) ? bi1 : bi2;
    __half*       Ch   = (blockIdx.z == 0) ? H0  : (blockIdx.z == 1) ? H1  : H2;

    const int tid    = threadIdx.x;
    const int wid    = tid >> 5;
    const int lane   = tid & 31;
    const int warp_m = wid >> 2;
    const int warp_n = wid & 3;
    const int g      = lane >> 2;
    const int t4     = lane & 3;

    const int row0 = blockIdx.y * MBM;
    const int col0 = blockIdx.x * MBN;

    const __half* gA = A + (size_t)row0 * K;
    const __half* gW = W + (size_t)col0 * K;

    const int lrow = tid >> 3;
    const int lch  = tid & 7;

    const uint32_t a_lane = (uint32_t)((warp_m * 64 + (lane & 15)) * APADH + ((lane >> 4) << 2));
    const uint32_t b_lane = (uint32_t)((warp_n * 64 + (lane & 7) + ((lane >> 4) << 3)) * APADH
                                       + (((lane >> 3) & 1) << 2));

    float acc[4][8][4];
    #pragma unroll
    for (int mt = 0; mt < 4; mt++)
        #pragma unroll
        for (int nt = 0; nt < 8; nt++)
            #pragma unroll
            for (int j = 0; j < 4; j++) acc[mt][nt][j] = 0.0f;

    const int NT = K / MBK;

    auto load_stage = [&](int buf, int kt) {
        const size_t kof = (size_t)kt * MBK + lch * 8;
        const uint32_t da = sAb + (buf * ASTG) * 4;
        const uint32_t db = sBb + (buf * BSTG) * 4;
        #pragma unroll
        for (int i = 0; i < 4; i++) {
            const int r = lrow + 32 * i;
            cp16(da + (r * APADH + lch * 4) * 4, gA + (size_t)r * K + kof);
        }
        #pragma unroll
        for (int i = 0; i < 8; i++) {
            const int r = lrow + 32 * i;
            cp16(db + (r * APADH + lch * 4) * 4, gW + (size_t)r * K + kof);
        }
    };

    load_stage(0, 0);
    CP_COMMIT();
    load_stage(1, 1);
    CP_COMMIT();

    int buf = 0;
    for (int t = 0; t < NT; t++) {
        CP_WAIT1();
        __syncthreads();

        const uint32_t abase = sAb + (buf * ASTG + a_lane) * 4;
        const uint32_t bbase = sBb + (buf * BSTG + b_lane) * 4;

        #pragma unroll
        for (int ks = 0; ks < 4; ks++) {
            uint32_t a[4][4], bb[4][4];
            #pragma unroll
            for (int mt = 0; mt < 4; mt++)
                LDMX4(a[mt], abase + (mt * 16 * APADH + ks * 8) * 4);
            #pragma unroll
            for (int ntp = 0; ntp < 4; ntp++)
                LDMX4(bb[ntp], bbase + (ntp * 16 * APADH + ks * 8) * 4);
            #pragma unroll
            for (int mt = 0; mt < 4; mt++)
                #pragma unroll
                for (int ntp = 0; ntp < 4; ntp++) {
                    mma_f16(acc[mt][2 * ntp],     a[mt], bb[ntp][0], bb[ntp][1]);
                    mma_f16(acc[mt][2 * ntp + 1], a[mt], bb[ntp][2], bb[ntp][3]);
                }
        }

        if (t + 2 < NT) {
            load_stage((buf + 2 >= NSTAGE) ? buf + 2 - NSTAGE : buf + 2, t + 2);
        }
        CP_COMMIT();
        buf = (buf + 1 == NSTAGE) ? 0 : buf + 1;
    }

    const int rb = row0 + warp_m * 64 + g;
    const int cb = col0 + warp_n * 64 + t4 * 2;
    #pragma unroll
    for (int mt = 0; mt < 4; mt++) {
        const int r = rb + mt * 16;
        #pragma unroll
        for (int nt = 0; nt < 8; nt++) {
            const int c = cb + nt * 8;
            const float2 bv = *(const float2*)(bias + c);
            float2 v0, v1;
            v0.x = acc[mt][nt][0] + bv.x;
            v0.y = acc[mt][nt][1] + bv.y;
            v1.x = acc[mt][nt][2] + bv.x;
            v1.y = acc[mt][nt][3] + bv.y;
            if (mode == 2) {
                const float2 r0 = *(const float2*)(resid + (size_t)r * ldc + c);
                const float2 r1 = *(const float2*)(resid + (size_t)(r + 8) * ldc + c);
                v0.x += r0.x; v0.y += r0.y;
                v1.x += r1.x; v1.y += r1.y;
                *(float2*)(Cf + (size_t)r * ldc + c)       = v0;
                *(float2*)(Cf + (size_t)(r + 8) * ldc + c) = v1;
            } else {
                if (mode == 1) {
                    v0.x = fmaxf(v0.x, 0.0f); v0.y = fmaxf(v0.y, 0.0f);
                    v1.x = fmaxf(v1.x, 0.0f); v1.y = fmaxf(v1.y, 0.0f);
                }
                __half2 h0 = __floats2half2_rn(v0.x, v0.y);
                __half2 h1 = __floats2half2_rn(v1.x, v1.y);
                *(uint32_t*)(Ch + (size_t)r * ldc + c)       = *(uint32_t*)&h0;
                *(uint32_t*)(Ch + (size_t)(r + 8) * ldc + c) = *(uint32_t*)&h1;
            }
        }
    }
}

// ---------------------------------------------------------------------------
// LayerNorm — half output (+ fp32 residual in/out, mask) — unchanged
// ---------------------------------------------------------------------------
__global__ __launch_bounds__(256) void ln_kernel(
    const float* __restrict__ x,
    const float* __restrict__ resid,
    float*       __restrict__ out_res,
    __half*      __restrict__ out_norm,
    const float* __restrict__ alpha,
    const float* __restrict__ beta,
    int apply_mask)
{
    __shared__ float red[256];
    const int n   = blockIdx.x;
    const int tid = threadIdx.x;
    const size_t off = (size_t)n * DD;
    const int d4 = tid * 4;

    float4 xv = *(const float4*)(x + off + d4);
    if (resid) {
        float4 rv = *(const float4*)(resid + off + d4);
        xv.x += rv.x; xv.y += rv.y; xv.z += rv.z; xv.w += rv.w;
    }
    if (out_res) *(float4*)(out_res + off + d4) = xv;

    float s = xv.x + xv.y + xv.z + xv.w;
    red[tid] = s;
    __syncthreads();
    #pragma unroll
    for (int st = 128; st > 0; st >>= 1) {
        if (tid < st) red[tid] += red[tid + st];
        __syncthreads();
    }
    const float mu = red[0] * (1.0f / DD);
    __syncthreads();

    float dx0 = xv.x - mu, dx1 = xv.y - mu, dx2 = xv.z - mu, dx3 = xv.w - mu;
    red[tid] = dx0*dx0 + dx1*dx1 + dx2*dx2 + dx3*dx3;
    __syncthreads();
    #pragma unroll
    for (int st = 128; st > 0; st >>= 1) {
        if (tid < st) red[tid] += red[tid + st];
        __syncthreads();
    }
    const float var = red[0] * (1.0f / (DD - 1));
    const float inv = 1.0f / (sqrtf(var) + EPS);

    float4 av = *(const float4*)(alpha + d4);
    float4 bv = *(const float4*)(beta  + d4);
    float4 y;
    y.x = av.x * dx0 * inv + bv.x;
    y.y = av.y * dx1 * inv + bv.y;
    y.z = av.z * dx2 * inv + bv.z;
    y.w = av.w * dx3 * inv + bv.w;
    if (apply_mask) {
        if (y.x < THRESH) y.x = 0.0f;
        if (y.y < THRESH) y.y = 0.0f;
        if (y.z < THRESH) y.z = 0.0f;
        if (y.w < THRESH) y.w = 0.0f;
    }
    __half2 h0 = __floats2half2_rn(y.x, y.y);
    __half2 h1 = __floats2half2_rn(y.z, y.w);
    uint2 pk;
    pk.x = *(uint32_t*)&h0;
    pk.y = *(uint32_t*)&h1;
    *(uint2*)(out_norm + off + d4) = pk;
}

// ---------------------------------------------------------------------------
// FlashAttention-2 style fp16 attention.
// 128 q-rows/CTA, 8 warps, warp tile 16x64 (full row per warp ->
// warp-local softmax via shfl, no S/P smem). K/V double-buffered cp.async.
// ---------------------------------------------------------------------------
#define FHPAD 36                              // u32 per 64-half row
#define FQ_U32  (128 * FHPAD)                 // Q tile u32
#define FKV_U32 (64 * FHPAD)                  // one K or V stage u32
#define SM_Q  0
#define SM_K0 (FQ_U32)
#define SM_V0 (FQ_U32 + 2 * FKV_U32)
#define FATTN_BYTES ((FQ_U32 + 4 * FKV_U32) * 4)   // 55296 B

__global__ __launch_bounds__(256, 2) void attn_mma(
    const __half* __restrict__ Q,
    const __half* __restrict__ Km,
    const __half* __restrict__ Vm,
    float*        __restrict__ O)
{
    extern __shared__ __align__(16) uint32_t smu[];
    const uint32_t sb = smem_u32(smu);

    const int qb  = blockIdx.x;               // 0..15
    const int bh  = blockIdx.y;               // 0..63
    const int b   = bh >> 4;
    const int h   = bh & 15;
    const int tid = threadIdx.x;
    const int lane = tid & 31;
    const int wid  = tid >> 5;                // warp owns rows wid*16..+15
    const int g    = lane >> 2;
    const int t4   = lane & 3;

    const size_t base = (size_t)b * SS * DD + (size_t)h * DH;
    const int q0 = qb * 128;

    // lane base offsets (u32)
    const uint32_t qa_lane = (uint32_t)((wid * 16 + (lane & 15)) * FHPAD + ((lane >> 4) << 2));
    const uint32_t kb_lane = (uint32_t)(((lane & 7) + ((lane >> 4) << 3)) * FHPAD
                                        + (((lane >> 3) & 1) << 2));
    const uint32_t vb_lane = (uint32_t)(((lane & 7) + (((lane >> 3) & 1) << 3)) * FHPAD
                                        + ((lane >> 4) << 2));

    // issue Q load (G1)
    #pragma unroll
    for (int i = 0; i < 4; i++) {
        const int t = tid + 256 * i;
        const int r = t >> 3, c = t & 7;
        cp16(sb + (SM_Q + r * FHPAD + c * 4) * 4,
             Q + base + (size_t)(q0 + r) * DD + c * 8);
    }
    CP_COMMIT();

    auto load_kv = [&](int s, int kt) {
        const int k0 = kt * 64;
        #pragma unroll
        for (int i = 0; i < 2; i++) {
            const int t = tid + 256 * i;
            const int r = t >> 3, c = t & 7;
            const uint32_t so = (r * FHPAD + c * 4) * 4;
            cp16(sb + (SM_K0 + s * FKV_U32) * 4 + so,
                 Km + base + (size_t)(k0 + r) * DD + c * 8);
            cp16(sb + (SM_V0 + s * FKV_U32) * 4 + so,
                 Vm + base + (size_t)(k0 + r) * DD + c * 8);
        }
    };

    load_kv(0, 0); CP_COMMIT();   // G2
    load_kv(1, 1); CP_COMMIT();   // G3

    // wait for Q (G1), preload Q fragments
    CP_WAIT2();
    __syncthreads();
    uint32_t qf[4][4];
    #pragma unroll
    for (int ks = 0; ks < 4; ks++)
        LDMX4(qf[ks], sb + (SM_Q + qa_lane + ks * 8) * 4);

    float m0 = -1e30f, m1 = -1e30f, l0 = 0.0f, l1 = 0.0f;
    float acc_o[8][4];
    #pragma unroll
    for (int nt = 0; nt < 8; nt++)
        #pragma unroll
        for (int j = 0; j < 4; j++) acc_o[nt][j] = 0.0f;

    for (int kt = 0; kt < SS / 64; kt++) {
        CP_WAIT1();
        __syncthreads();
        const int s = kt & 1;

        // --- S = Q K^T (warp computes 16 rows x 64 keys) ---
        float accs[8][4];
        #pragma unroll
        for (int nt = 0; nt < 8; nt++)
            #pragma unroll
            for (int j = 0; j < 4; j++) accs[nt][j] = 0.0f;

        const uint32_t kbase = sb + (SM_K0 + s * FKV_U32 + kb_lane) * 4;
        #pragma unroll
        for (int ks = 0; ks < 4; ks++) {
            #pragma unroll
            for (int nt16 = 0; nt16 < 4; nt16++) {
                uint32_t bb[4];
                LDMX4(bb, kbase + (nt16 * 16 * FHPAD + ks * 8) * 4);
                mma_f16(accs[2 * nt16],     qf[ks], bb[0], bb[1]);
                mma_f16(accs[2 * nt16 + 1], qf[ks], bb[2], bb[3]);
            }
        }

        // --- warp-local online softmax (rows g and g+8) ---
        float nm0 = -1e30f, nm1 = -1e30f;
        #pragma unroll
        for (int nt = 0; nt < 8; nt++) {
            accs[nt][0] *= SCALE; accs[nt][1] *= SCALE;
            accs[nt][2] *= SCALE; accs[nt][3] *= SCALE;
            nm0 = fmaxf(nm0, fmaxf(accs[nt][0], accs[nt][1]));
            nm1 = fmaxf(nm1, fmaxf(accs[nt][2], accs[nt][3]));
        }
        nm0 = fmaxf(nm0, __shfl_xor_sync(0xffffffff, nm0, 1));
        nm0 = fmaxf(nm0, __shfl_xor_sync(0xffffffff, nm0, 2));
        nm1 = fmaxf(nm1, __shfl_xor_sync(0xffffffff, nm1, 1));
        nm1 = fmaxf(nm1, __shfl_xor_sync(0xffffffff, nm1, 2));
        nm0 = fmaxf(m0, nm0);
        nm1 = fmaxf(m1, nm1);
        const float corr0 = __expf(m0 - nm0);
        const float corr1 = __expf(m1 - nm1);
        m0 = nm0; m1 = nm1;

        float s0 = 0.0f, s1 = 0.0f;
        uint32_t ph[8][2];
        #pragma unroll
        for (int nt = 0; nt < 8; nt++) {
            const float e0 = __expf(accs[nt][0] - m0);
            const float e1 = __expf(accs[nt][1] - m0);
            const float e2 = __expf(accs[nt][2] - m1);
            const float e3 = __expf(accs[nt][3] - m1);
            s0 += e0 + e1; s1 += e2 + e3;
            __half2 h01 = __floats2half2_rn(e0, e1);
            __half2 h23 = __floats2half2_rn(e2, e3);
            ph[nt][0] = *(uint32_t*)&h01;
            ph[nt][1] = *(uint32_t*)&h23;
        }
        s0 += __shfl_xor_sync(0xffffffff, s0, 1);
        s0 += __shfl_xor_sync(0xffffffff, s0, 2);
        s1 += __shfl_xor_sync(0xffffffff, s1, 1);
        s1 += __shfl_xor_sync(0xffffffff, s1, 2);
        l0 = l0 * corr0 + s0;
        l1 = l1 * corr1 + s1;

        #pragma unroll
        for (int nt = 0; nt < 8; nt++) {
            acc_o[nt][0] *= corr0; acc_o[nt][1] *= corr0;
            acc_o[nt][2] *= corr1; acc_o[nt][3] *= corr1;
        }

        // --- acc_o += P V (P from registers, V via ldmatrix.trans) ---
        const uint32_t vbase = sb + (SM_V0 + s * FKV_U32 + vb_lane) * 4;
        #pragma unroll
        for (int ks = 0; ks < 4; ks++) {
            const uint32_t a[4] = { ph[2 * ks][0], ph[2 * ks][1],
                                    ph[2 * ks + 1][0], ph[2 * ks + 1][1] };
            #pragma unroll
            for (int d16 = 0; d16 < 4; d16++) {
                uint32_t bb[4];
                LDMX4T(bb, vbase + (ks * 16 * FHPAD + d16 * 8) * 4);
                mma_f16(acc_o[2 * d16],     a, bb[0], bb[1]);
                mma_f16(acc_o[2 * d16 + 1], a, bb[2], bb[3]);
            }
        }

        __syncthreads();
        if (kt + 2 < SS / 64) load_kv(s, kt + 2);
        CP_COMMIT();
    }

    // epilogue: divide by l, store fp32
    const float li0 = 1.0f / l0;
    const float li1 = 1.0f / l1;
    const int r0 = q0 + wid * 16 + g;
    const size_t ro0 = base + (size_t)r0 * DD;
    const size_t ro1 = base + (size_t)(r0 + 8) * DD;
    #pragma unroll
    for (int nt = 0; nt < 8; nt++) {
        const int c = nt * 8 + 2 * t4;
        float2 lo, hi;
        lo.x = acc_o[nt][0] * li0; lo.y = acc_o[nt][1] * li0;
        hi.x = acc_o[nt][2] * li1; hi.y = acc_o[nt][3] * li1;
        *(float2*)(O + ro0 + c) = lo;
        *(float2*)(O + ro1 + c) = hi;
    }
}

// ---------------------------------------------------------------------------
// launch
// ---------------------------------------------------------------------------
extern "C" void kernel_launch(void* const* d_in, const int* in_sizes, int n_in,
                              void* d_out, int out_size)
{
    const float* x      = (const float*)d_in[0];
    const float* alpha1 = (const float*)d_in[1];
    const float* bias1  = (const float*)d_in[2];
    const float* alpha2 = (const float*)d_in[3];
    const float* bias2  = (const float*)d_in[4];
    const float* wq     = (const float*)d_in[5];
    const float* bq     = (const float*)d_in[6];
    const float* wk     = (const float*)d_in[7];
    const float* bk     = (const float*)d_in[8];
    const float* wv     = (const float*)d_in[9];
    const float* bv     = (const float*)d_in[10];
    const float* w1     = (const float*)d_in[11];
    const float* b1     = (const float*)d_in[12];
    const float* w2     = (const float*)d_in[13];
    const float* b2     = (const float*)d_in[14];
    float* out = (float*)d_out;

    __half *p_x2, *p_q, *p_k, *p_v, *p_x2b, *p_h;
    __half *p_wqh, *p_wkh, *p_wvh, *p_w1h, *p_w2h;
    float *p_attn, *p_xres;
    cudaGetSymbolAddress((void**)&p_x2,   g_x2);
    cudaGetSymbolAddress((void**)&p_q,    g_q);
    cudaGetSymbolAddress((void**)&p_k,    g_k);
    cudaGetSymbolAddress((void**)&p_v,    g_v);
    cudaGetSymbolAddress((void**)&p_attn, g_attn);
    cudaGetSymbolAddress((void**)&p_xres, g_xres);
    cudaGetSymbolAddress((void**)&p_x2b,  g_x2b);
    cudaGetSymbolAddress((void**)&p_h,    g_h);
    cudaGetSymbolAddress((void**)&p_wqh,  g_wqh);
    cudaGetSymbolAddress((void**)&p_wkh,  g_wkh);
    cudaGetSymbolAddress((void**)&p_wvh,  g_wvh);
    cudaGetSymbolAddress((void**)&p_w1h,  g_w1h);
    cudaGetSymbolAddress((void**)&p_w2h,  g_w2h);

    cudaFuncSetAttribute(attn_mma,
                         cudaFuncAttributeMaxDynamicSharedMemorySize, FATTN_BYTES);
    cudaFuncSetAttribute(mma_gemm,
                         cudaFuncAttributeMaxDynamicSharedMemorySize, GSMEM_BYTES);

    // 0) convert weights to half
    const int nqkv4 = DD * DD / 4, nff4 = FF * DD / 4;
    cvt_f2h_kernel<<<(nqkv4 + 255) / 256, 256>>>(wq, p_wqh, nqkv4);
    cvt_f2h_kernel<<<(nqkv4 + 255) / 256, 256>>>(wk, p_wkh, nqkv4);
    cvt_f2h_kernel<<<(nqkv4 + 255) / 256, 256>>>(wv, p_wvh, nqkv4);
    cvt_f2h_kernel<<<(nff4  + 255) / 256, 256>>>(w1, p_w1h, nff4);
    cvt_f2h_kernel<<<(nff4  + 255) / 256, 256>>>(w2, p_w2h, nff4);

    // 1) norm1 (half out)
    ln_kernel<<<NN, 256>>>(x, nullptr, nullptr, p_x2, alpha1, bias1, 0);

    // 2) fused q,k,v projections (half out)
    mma_gemm<<<dim3(DD / MBN, NN / MBM, 3), 256, GSMEM_BYTES>>>(
        p_x2, p_wqh, p_wkh, p_wvh, bq, bk, bv, nullptr,
        p_q, p_k, p_v, nullptr, DD, DD, 0);

    // 3) attention (FA2-style, fp32 out)
    attn_mma<<<dim3(SS / 128, BB * HH), 256, FATTN_BYTES>>>(p_q, p_k, p_v, p_attn);

    // 4) residual + norm2 + mask (half out, fp32 resid out)
    ln_kernel<<<NN, 256>>>(x, p_attn, p_xres, p_x2b, alpha2, bias2, 1);

    // 5) ffn1 + relu (half out)
    mma_gemm<<<dim3(FF / MBN, NN / MBM, 1), 256, GSMEM_BYTES>>>(
        p_x2b, p_w1h, p_w1h, p_w1h, b1, b1, b1, nullptr,
        p_h, p_h, p_h, nullptr, DD, FF, 1);

    // 6) ffn2 + bias + residual -> out (fp32)
    mma_gemm<<<dim3(DD / MBN, NN / MBM, 1), 256, GSMEM_BYTES>>>(
        p_h, p_w2h, p_w2h, p_w2h, b2, b2, b2, p_xres,
        nullptr, nullptr, nullptr, out, FF, DD, 2);
}